// round 5
// baseline (speedup 1.0000x reference)
#include <cuda_runtime.h>
#include <cuda_bf16.h>
#include <cstdint>

#define BATCH 16384
#define DIM   1024
#define NLAY  6
#define NMC   64
#define HW    16

#define BM 128
#define BN 128
#define BK 32
#define AST 40     // A smem row stride (bf16), padded
#define WST 136    // W smem row stride (bf16), padded
#define NST 4      // cp.async pipeline stages
#define NTCH (DIM / BK)   // 32 K-chunks

#define SA_B (BM * AST * 2)               // 10240 B per A buffer
#define SW_B (BK * WST * 2)               // 8704 B per W buffer
#define STG_B (2 * SA_B + 2 * SW_B)       // 37888 B per stage
#define SMEM_BYTES (NST * STG_B)          // 151552

// ---------------- static device scratch ----------------
#define SQ ((size_t)1048576)
#define OFF_WEI ((size_t)0)
#define OFF_LAT ((size_t)(6 * 2048 * 1024))
#define OFF_V   (OFF_LAT + 6 * SQ)
#define OFF_O   (OFF_V + 6 * SQ)
#define OFF_FB  (OFF_O + 6 * SQ)
#define WT_TOT  (OFF_FB + 5 * SQ)

__device__ __nv_bfloat16 g_w_h[WT_TOT];   // weights hi, [mat][k][n] layout
__device__ __nv_bfloat16 g_w_l[WT_TOT];   // weights lo
__device__ float g_bei[NLAY * 2 * DIM];

__device__ __nv_bfloat16 g_actA_h[(size_t)BATCH * DIM];
__device__ __nv_bfloat16 g_actA_l[(size_t)BATCH * DIM];
__device__ __nv_bfloat16 g_actB_h[(size_t)BATCH * DIM];
__device__ __nv_bfloat16 g_actB_l[(size_t)BATCH * DIM];
__device__ __nv_bfloat16 g_ei_h[(size_t)BATCH * 2 * DIM];
__device__ __nv_bfloat16 g_ei_l[(size_t)BATCH * 2 * DIM];
__device__ __nv_bfloat16 g_mc_h[(size_t)BATCH * DIM];
__device__ __nv_bfloat16 g_mc_l[(size_t)BATCH * DIM];
__device__ __nv_bfloat16 g_lat_h[(size_t)BATCH * DIM];
__device__ __nv_bfloat16 g_lat_l[(size_t)BATCH * DIM];

// ---------------- helpers ----------------
__device__ __forceinline__ uint32_t cvt_bf16x2(float lo_elem, float hi_elem) {
    uint32_t r;
    asm("cvt.rn.bf16x2.f32 %0, %1, %2;" : "=r"(r) : "f"(hi_elem), "f"(lo_elem));
    return r;
}
__device__ __forceinline__ void split2(float a, float b, uint32_t& h, uint32_t& l) {
    h = cvt_bf16x2(a, b);
    float ha = __uint_as_float(h << 16);
    float hb = __uint_as_float(h & 0xffff0000u);
    l = cvt_bf16x2(a - ha, b - hb);
}
__device__ __forceinline__ float2 bf2f(uint32_t u) {
    __nv_bfloat162 h = *(__nv_bfloat162*)&u;
    return make_float2(__bfloat162float(h.x), __bfloat162float(h.y));
}
__device__ __forceinline__ void cp16(uint32_t dst, const void* src) {
    asm volatile("cp.async.cg.shared.global [%0], [%1], 16;" :: "r"(dst), "l"(src));
}
__device__ __forceinline__ void ldsm4(uint32_t addr, uint32_t& r0, uint32_t& r1,
                                      uint32_t& r2, uint32_t& r3) {
    asm volatile("ldmatrix.sync.aligned.m8n8.x4.shared.b16 {%0,%1,%2,%3}, [%4];"
                 : "=r"(r0), "=r"(r1), "=r"(r2), "=r"(r3) : "r"(addr));
}
__device__ __forceinline__ void ldsm4t(uint32_t addr, uint32_t& r0, uint32_t& r1,
                                       uint32_t& r2, uint32_t& r3) {
    asm volatile("ldmatrix.sync.aligned.m8n8.x4.trans.shared.b16 {%0,%1,%2,%3}, [%4];"
                 : "=r"(r0), "=r"(r1), "=r"(r2), "=r"(r3) : "r"(addr));
}
__device__ __forceinline__ void mma16816(float* c, const uint32_t* a, const uint32_t* b) {
    asm volatile(
        "mma.sync.aligned.m16n8k16.row.col.f32.bf16.bf16.f32 "
        "{%0,%1,%2,%3}, {%4,%5,%6,%7}, {%8,%9}, {%0,%1,%2,%3};"
        : "+f"(c[0]), "+f"(c[1]), "+f"(c[2]), "+f"(c[3])
        : "r"(a[0]), "r"(a[1]), "r"(a[2]), "r"(a[3]), "r"(b[0]), "r"(b[1]));
}

// ---------------- pack kernels ----------------
// We/Wi [L,NMC,D,H] fp32 -> fused [l][k][n=2048] bf16 hi/lo (n<1024: We, else Wi)
__global__ void pack_wei(const float* __restrict__ We, const float* __restrict__ Wi) {
    size_t i = (size_t)blockIdx.x * blockDim.x + threadIdx.x;
    const size_t total = (size_t)NLAY * DIM * 2 * DIM;
    if (i >= total) return;
    int l = (int)(i / ((size_t)DIM * 2 * DIM));
    size_t r = i % ((size_t)DIM * 2 * DIM);
    int k = (int)(r / (2 * DIM));
    int n = (int)(r % (2 * DIM));
    const float* src;
    int nn;
    if (n < DIM) { src = We; nn = n; } else { src = Wi; nn = n - DIM; }
    int m = nn / HW, h = nn % HW;
    float v = src[(((size_t)l * NMC + m) * DIM + k) * HW + h];
    __nv_bfloat16 hb = __float2bfloat16(v);
    g_w_h[OFF_WEI + i] = hb;
    g_w_l[OFF_WEI + i] = __float2bfloat16(v - __bfloat162float(hb));
}

// elementwise fp32 -> bf16 hi/lo
__global__ void pack_split(const float* __restrict__ src, __nv_bfloat16* __restrict__ dh,
                           __nv_bfloat16* __restrict__ dl, size_t total) {
    size_t i = ((size_t)blockIdx.x * blockDim.x + threadIdx.x) * 4;
    if (i >= total) return;
    float4 v = *(const float4*)(src + i);
    uint32_t h0, l0, h1, l1;
    split2(v.x, v.y, h0, l0);
    split2(v.z, v.w, h1, l1);
    *(uint2*)(dh + i) = make_uint2(h0, h1);
    *(uint2*)(dl + i) = make_uint2(l0, l1);
}

__global__ void pack_bias_kernel(const float* __restrict__ be, const float* __restrict__ bi) {
    int i = blockIdx.x * blockDim.x + threadIdx.x;
    if (i >= NLAY * 2 * DIM) return;
    int l = i / (2 * DIM);
    int n = i % (2 * DIM);
    g_bei[i] = (n < DIM) ? be[l * DIM + n] : bi[l * DIM + (n - DIM)];
}

// ---------------- bf16x3 HMMA GEMM, cp.async pipelined ----------------
// C[128x128/CTA] = epi( A[M,1024] @ W[1024,N] + bias ), A/W pre-split bf16 hi/lo.
// EPI 0: split only  1: relu+split  2: fp32 out + split  3: fp32 out += + split
template <int EPI>
__global__ __launch_bounds__(256)
void bgemm(const __nv_bfloat16* __restrict__ Ah, const __nv_bfloat16* __restrict__ Al,
           const __nv_bfloat16* __restrict__ Wh, const __nv_bfloat16* __restrict__ Wl,
           const float* __restrict__ bias,
           __nv_bfloat16* __restrict__ oHi, __nv_bfloat16* __restrict__ oLo,
           float* __restrict__ oF, int N) {
    extern __shared__ char smem[];
    const uint32_t smem_u = (uint32_t)__cvta_generic_to_shared(smem);
    const int tid = threadIdx.x;
    const int lane = tid & 31, wid = tid >> 5;
    const int wm = wid >> 2, wn = wid & 3;
    const int bx = blockIdx.x, by = blockIdx.y;

    const char* pAh = (const char*)Ah + (size_t)by * BM * (DIM * 2);
    const char* pAl = (const char*)Al + (size_t)by * BM * (DIM * 2);
    const char* pWh = (const char*)Wh + (size_t)bx * BN * 2;
    const char* pWl = (const char*)Wl + (size_t)bx * BN * 2;
    const size_t wrow_b = (size_t)N * 2;

    // loader mapping
    const int arow = tid >> 2, ac = tid & 3;        // A: 2 iters -> rows via idx
    // (recomputed per-iter below from idx)

    auto load_chunk = [&](int c) {
        const uint32_t sb = smem_u + (uint32_t)(c & (NST - 1)) * STG_B;
#pragma unroll
        for (int i = 0; i < 2; i++) {
            int idx = i * 256 + tid;
            int r = idx >> 2, cc = idx & 3;          // A: 128 rows x 4 chunks
            uint32_t soff = (uint32_t)(r * (AST * 2) + cc * 16);
            size_t g = (size_t)r * (DIM * 2) + (size_t)c * (BK * 2) + (size_t)cc * 16;
            cp16(sb + soff,        pAh + g);
            cp16(sb + SA_B + soff, pAl + g);
        }
#pragma unroll
        for (int i = 0; i < 2; i++) {
            int idx = i * 256 + tid;
            int r = idx >> 4, cc = idx & 15;         // W: 32 rows x 16 chunks
            uint32_t soff = (uint32_t)(r * (WST * 2) + cc * 16);
            size_t g = (size_t)(c * BK + r) * wrow_b + (size_t)cc * 16;
            cp16(sb + 2 * SA_B + soff,        pWh + g);
            cp16(sb + 2 * SA_B + SW_B + soff, pWl + g);
        }
        asm volatile("cp.async.commit_group;" ::: "memory");
    };
    (void)arow; (void)ac;

    float acc[4][4][4];
#pragma unroll
    for (int mt = 0; mt < 4; mt++)
#pragma unroll
        for (int nt = 0; nt < 4; nt++)
#pragma unroll
            for (int q = 0; q < 4; q++) acc[mt][nt][q] = 0.f;

    load_chunk(0);
    load_chunk(1);
    load_chunk(2);

    const int lrow = lane & 15;
    const int lcol8 = (lane >> 4) * 8;

    for (int t = 0; t < NTCH; t++) {
        if (t < NTCH - 2)      asm volatile("cp.async.wait_group 2;" ::: "memory");
        else if (t == NTCH - 2) asm volatile("cp.async.wait_group 1;" ::: "memory");
        else                    asm volatile("cp.async.wait_group 0;" ::: "memory");
        __syncthreads();
        if (t + 3 < NTCH) load_chunk(t + 3);

        const uint32_t sb = smem_u + (uint32_t)(t & (NST - 1)) * STG_B;
        const uint32_t sAh_u = sb, sAl_u = sb + SA_B;
        const uint32_t sWh_u = sb + 2 * SA_B, sWl_u = sb + 2 * SA_B + SW_B;

#pragma unroll
        for (int ks = 0; ks < 2; ks++) {
            uint32_t bh[4][2], bl[4][2];
#pragma unroll
            for (int np = 0; np < 2; np++) {
                uint32_t off = (uint32_t)((ks * 16 + lrow) * WST + wn * 32 + np * 16 + lcol8) * 2;
                uint32_t r0, r1, r2, r3;
                ldsm4t(sWh_u + off, r0, r1, r2, r3);
                bh[np * 2][0] = r0; bh[np * 2][1] = r1;
                bh[np * 2 + 1][0] = r2; bh[np * 2 + 1][1] = r3;
                ldsm4t(sWl_u + off, r0, r1, r2, r3);
                bl[np * 2][0] = r0; bl[np * 2][1] = r1;
                bl[np * 2 + 1][0] = r2; bl[np * 2 + 1][1] = r3;
            }
#pragma unroll
            for (int mt = 0; mt < 4; mt++) {
                uint32_t aoff = (uint32_t)((wm * 64 + mt * 16 + lrow) * AST + ks * 16 + lcol8) * 2;
                uint32_t ah[4], al[4];
                ldsm4(sAh_u + aoff, ah[0], ah[1], ah[2], ah[3]);
                ldsm4(sAl_u + aoff, al[0], al[1], al[2], al[3]);
#pragma unroll
                for (int nt = 0; nt < 4; nt++) mma16816(acc[mt][nt], ah, bh[nt]);
#pragma unroll
                for (int nt = 0; nt < 4; nt++) mma16816(acc[mt][nt], ah, bl[nt]);
#pragma unroll
                for (int nt = 0; nt < 4; nt++) mma16816(acc[mt][nt], al, bh[nt]);
            }
        }
    }

    // ---------------- epilogue ----------------
    const int g = lane >> 2;
    const int tg = lane & 3;
#pragma unroll
    for (int mt = 0; mt < 4; mt++) {
        const int r0 = by * BM + wm * 64 + mt * 16 + g;
#pragma unroll
        for (int nt = 0; nt < 4; nt++) {
            const int col = bx * BN + wn * 32 + nt * 8 + tg * 2;
            float2 bv = *(const float2*)(bias + col);
            float2 v0, v1;
            v0.x = acc[mt][nt][0] + bv.x;  v0.y = acc[mt][nt][1] + bv.y;
            v1.x = acc[mt][nt][2] + bv.x;  v1.y = acc[mt][nt][3] + bv.y;
            if (EPI == 1) {
                v0.x = fmaxf(v0.x, 0.f); v0.y = fmaxf(v0.y, 0.f);
                v1.x = fmaxf(v1.x, 0.f); v1.y = fmaxf(v1.y, 0.f);
            }
            if (EPI >= 2) {
                float* p0 = oF + (size_t)r0 * N + col;
                float* p1 = oF + (size_t)(r0 + 8) * N + col;
                if (EPI == 3) {
                    float2 o0 = *(const float2*)p0;
                    float2 o1 = *(const float2*)p1;
                    v0.x += o0.x; v0.y += o0.y; v1.x += o1.x; v1.y += o1.y;
                }
                *(float2*)p0 = v0;
                *(float2*)p1 = v1;
            }
            uint32_t h0, l0, h1, l1;
            split2(v0.x, v0.y, h0, l0);
            split2(v1.x, v1.y, h1, l1);
            *(uint32_t*)(oHi + (size_t)r0 * N + col)       = h0;
            *(uint32_t*)(oLo + (size_t)r0 * N + col)       = l0;
            *(uint32_t*)(oHi + (size_t)(r0 + 8) * N + col) = h1;
            *(uint32_t*)(oLo + (size_t)(r0 + 8) * N + col) = l1;
        }
    }
}

// ---------------- minicolumn block-diag (bf16 hi/lo IO) ----------------
__global__ __launch_bounds__(256)
void mc_kernel(const __nv_bfloat16* __restrict__ eH, const __nv_bfloat16* __restrict__ eL,
               const float* __restrict__ Wl, const float* __restrict__ bl,
               __nv_bfloat16* __restrict__ mH, __nv_bfloat16* __restrict__ mL) {
    __shared__ float sW[HW * HW];
    __shared__ float sb[HW];
    const int m = blockIdx.y;
    if (threadIdx.x < HW * HW) sW[threadIdx.x] = Wl[m * HW * HW + threadIdx.x];
    if (threadIdx.x < HW)      sb[threadIdx.x] = bl[m * HW + threadIdx.x];
    __syncthreads();

    const int b = blockIdx.x * 256 + threadIdx.x;
    const size_t base = (size_t)b * (2 * DIM);

    float exc[HW], inh[HW];
#pragma unroll
    for (int part = 0; part < 2; part++) {
        size_t off = base + (part ? DIM : 0) + m * HW;
        uint4 hA = *(const uint4*)(eH + off);
        uint4 hB = *(const uint4*)(eH + off + 8);
        uint4 lA = *(const uint4*)(eL + off);
        uint4 lB = *(const uint4*)(eL + off + 8);
        uint32_t hw_[4] = {hA.x, hA.y, hA.z, hA.w};
        uint32_t hw2[4] = {hB.x, hB.y, hB.z, hB.w};
        uint32_t lw_[4] = {lA.x, lA.y, lA.z, lA.w};
        uint32_t lw2[4] = {lB.x, lB.y, lB.z, lB.w};
        float* dst = part ? inh : exc;
#pragma unroll
        for (int j = 0; j < 4; j++) {
            float2 h2 = bf2f(hw_[j]); float2 l2 = bf2f(lw_[j]);
            dst[j * 2 + 0] = h2.x + l2.x;
            dst[j * 2 + 1] = h2.y + l2.y;
            float2 h3 = bf2f(hw2[j]); float2 l3 = bf2f(lw2[j]);
            dst[8 + j * 2 + 0] = h3.x + l3.x;
            dst[8 + j * 2 + 1] = h3.y + l3.y;
        }
    }

    float out[HW];
#pragma unroll
    for (int k = 0; k < HW; k++) {
        float lat = sb[k];
#pragma unroll
        for (int h = 0; h < HW; h++) lat += inh[h] * sW[h * HW + k];
        out[k] = fmaxf(exc[k] - lat, 0.f);
    }

    uint32_t hu[8], lu[8];
#pragma unroll
    for (int p = 0; p < 8; p++) split2(out[2 * p], out[2 * p + 1], hu[p], lu[p]);
    size_t o = (size_t)b * DIM + m * HW;
    *(uint4*)(mH + o)     = make_uint4(hu[0], hu[1], hu[2], hu[3]);
    *(uint4*)(mH + o + 8) = make_uint4(hu[4], hu[5], hu[6], hu[7]);
    *(uint4*)(mL + o)     = make_uint4(lu[0], lu[1], lu[2], lu[3]);
    *(uint4*)(mL + o + 8) = make_uint4(lu[4], lu[5], lu[6], lu[7]);
}

// ---------------- driver ----------------
extern "C" void kernel_launch(void* const* d_in, const int* in_sizes, int n_in,
                              void* d_out, int out_size) {
    const float* x    = (const float*)d_in[0];
    const float* We   = (const float*)d_in[1];
    const float* be   = (const float*)d_in[2];
    const float* Wi   = (const float*)d_in[3];
    const float* bi   = (const float*)d_in[4];
    const float* Wl   = (const float*)d_in[5];
    const float* bl   = (const float*)d_in[6];
    const float* Wlat = (const float*)d_in[7];
    const float* blat = (const float*)d_in[8];
    const float* Wv   = (const float*)d_in[9];
    const float* bv   = (const float*)d_in[10];
    const float* Wo   = (const float*)d_in[11];
    const float* bo   = (const float*)d_in[12];
    const float* fbW  = (const float*)d_in[13];
    const float* fbb  = (const float*)d_in[14];
    float* out = (float*)d_out;

    const size_t BD = (size_t)BATCH * DIM;

    __nv_bfloat16 *w_h, *w_l, *actA_h, *actA_l, *actB_h, *actB_l;
    __nv_bfloat16 *ei_h, *ei_l, *mc_h, *mc_l, *lat_h, *lat_l;
    float* bei_p;
    cudaGetSymbolAddress((void**)&w_h, g_w_h);
    cudaGetSymbolAddress((void**)&w_l, g_w_l);
    cudaGetSymbolAddress((void**)&actA_h, g_actA_h);
    cudaGetSymbolAddress((void**)&actA_l, g_actA_l);
    cudaGetSymbolAddress((void**)&actB_h, g_actB_h);
    cudaGetSymbolAddress((void**)&actB_l, g_actB_l);
    cudaGetSymbolAddress((void**)&ei_h, g_ei_h);
    cudaGetSymbolAddress((void**)&ei_l, g_ei_l);
    cudaGetSymbolAddress((void**)&mc_h, g_mc_h);
    cudaGetSymbolAddress((void**)&mc_l, g_mc_l);
    cudaGetSymbolAddress((void**)&lat_h, g_lat_h);
    cudaGetSymbolAddress((void**)&lat_l, g_lat_l);
    cudaGetSymbolAddress((void**)&bei_p, g_bei);

    cudaFuncSetAttribute(bgemm<0>, cudaFuncAttributeMaxDynamicSharedMemorySize, SMEM_BYTES);
    cudaFuncSetAttribute(bgemm<1>, cudaFuncAttributeMaxDynamicSharedMemorySize, SMEM_BYTES);
    cudaFuncSetAttribute(bgemm<2>, cudaFuncAttributeMaxDynamicSharedMemorySize, SMEM_BYTES);
    cudaFuncSetAttribute(bgemm<3>, cudaFuncAttributeMaxDynamicSharedMemorySize, SMEM_BYTES);

    // ---- packs ----
    {
        size_t tw = (size_t)NLAY * DIM * 2 * DIM;
        pack_wei<<<(unsigned)((tw + 255) / 256), 256>>>(We, Wi);
        pack_split<<<(unsigned)(6 * SQ / 4 / 256), 256>>>(Wlat, w_h + OFF_LAT, w_l + OFF_LAT, 6 * SQ);
        pack_split<<<(unsigned)(6 * SQ / 4 / 256), 256>>>(Wv,   w_h + OFF_V,   w_l + OFF_V,   6 * SQ);
        pack_split<<<(unsigned)(6 * SQ / 4 / 256), 256>>>(Wo,   w_h + OFF_O,   w_l + OFF_O,   6 * SQ);
        pack_split<<<(unsigned)(5 * SQ / 4 / 256), 256>>>(fbW,  w_h + OFF_FB,  w_l + OFF_FB,  5 * SQ);
        pack_split<<<(unsigned)(BD / 4 / 256), 256>>>(x, actA_h, actA_l, BD);
        pack_bias_kernel<<<(NLAY * 2 * DIM + 255) / 256, 256>>>(be, bi);
    }

    dim3 blk(256);
    dim3 grid_wide(2 * DIM / BN, BATCH / BM);
    dim3 grid_sq(DIM / BN, BATCH / BM);
    dim3 grid_mc(BATCH / 256, NMC);

    for (int l = 0; l < NLAY; l++) {
        const size_t weOff = OFF_WEI + (size_t)l * 2048 * 1024;
        // exc|inh = relu(act @ Wei + bei)
        bgemm<1><<<grid_wide, blk, SMEM_BYTES>>>(actA_h, actA_l, w_h + weOff, w_l + weOff,
                                                 bei_p + l * 2048, ei_h, ei_l, nullptr, 2048);
        // mc = relu(exc - (inh @ Wl + bl))
        mc_kernel<<<grid_mc, blk>>>(ei_h, ei_l, Wl + (size_t)l * NMC * HW * HW,
                                    bl + (size_t)l * NMC * HW, mc_h, mc_l);
        // lateral = mc @ Wlat + blat
        bgemm<0><<<grid_sq, blk, SMEM_BYTES>>>(mc_h, mc_l, w_h + OFF_LAT + (size_t)l * SQ,
                                               w_l + OFF_LAT + (size_t)l * SQ,
                                               blat + (size_t)l * DIM, lat_h, lat_l, nullptr, 1024);
        // tmp = lateral @ Wv + bv
        bgemm<0><<<grid_sq, blk, SMEM_BYTES>>>(lat_h, lat_l, w_h + OFF_V + (size_t)l * SQ,
                                               w_l + OFF_V + (size_t)l * SQ,
                                               bv + (size_t)l * DIM, mc_h, mc_l, nullptr, 1024);
        // attended = tmp @ Wo + bo -> out[l] fp32 + next-layer act split
        bgemm<2><<<grid_sq, blk, SMEM_BYTES>>>(mc_h, mc_l, w_h + OFF_O + (size_t)l * SQ,
                                               w_l + OFF_O + (size_t)l * SQ,
                                               bo + (size_t)l * DIM, actA_h, actA_l,
                                               out + (size_t)l * BD, 1024);
    }

    // feedback: out[idx] += fb_in @ fbW[i] + fbb[i]; fb_in hi/lo ping-pongs
    __nv_bfloat16 *fin_h = actA_h, *fin_l = actA_l, *fout_h = actB_h, *fout_l = actB_l;
    for (int i = 0; i < NLAY - 1; i++) {
        int idx = NLAY - 2 - i;
        bgemm<3><<<grid_sq, blk, SMEM_BYTES>>>(fin_h, fin_l, w_h + OFF_FB + (size_t)i * SQ,
                                               w_l + OFF_FB + (size_t)i * SQ,
                                               fbb + (size_t)i * DIM, fout_h, fout_l,
                                               out + (size_t)idx * BD, 1024);
        __nv_bfloat16* t;
        t = fin_h; fin_h = fout_h; fout_h = t;
        t = fin_l; fin_l = fout_l; fout_l = t;
    }
}

// round 6
// speedup vs baseline: 1.1898x; 1.1898x over previous
#include <cuda_runtime.h>
#include <cuda_bf16.h>
#include <cstdint>

#define BATCH 16384
#define DIM   1024
#define NLAY  6
#define NMC   64
#define HW    16

#define BM 128
#define BN 128
#define BK 32
#define AST 40     // A smem row stride (bf16 elems)
#define WST 136    // W smem row stride (bf16 elems)
#define NTCH (DIM / BK)   // 32 K-chunks

#define SMEM_BYTES ((2 * BM * AST * 2 + 2 * BK * WST * 2) * 2)  // 75776

// ---------------- static device scratch ----------------
#define SQ ((size_t)1048576)
#define OFF_WEI ((size_t)0)
#define OFF_LAT ((size_t)(6 * 2048 * 1024))
#define OFF_V   (OFF_LAT + 6 * SQ)
#define OFF_O   (OFF_V + 6 * SQ)
#define OFF_FB  (OFF_O + 6 * SQ)
#define WT_TOT  (OFF_FB + 5 * SQ)

__device__ __nv_bfloat16 g_w_h[WT_TOT];   // weights hi, [mat][k][n]
__device__ __nv_bfloat16 g_w_l[WT_TOT];   // weights lo
__device__ float g_bei[NLAY * 2 * DIM];

__device__ __nv_bfloat16 g_actA_h[(size_t)BATCH * DIM];
__device__ __nv_bfloat16 g_actA_l[(size_t)BATCH * DIM];
__device__ __nv_bfloat16 g_actB_h[(size_t)BATCH * DIM];
__device__ __nv_bfloat16 g_actB_l[(size_t)BATCH * DIM];
__device__ __nv_bfloat16 g_ei_h[(size_t)BATCH * 2 * DIM];
__device__ __nv_bfloat16 g_ei_l[(size_t)BATCH * 2 * DIM];
__device__ __nv_bfloat16 g_mc_h[(size_t)BATCH * DIM];
__device__ __nv_bfloat16 g_mc_l[(size_t)BATCH * DIM];
__device__ __nv_bfloat16 g_lat_h[(size_t)BATCH * DIM];
__device__ __nv_bfloat16 g_lat_l[(size_t)BATCH * DIM];

// ---------------- helpers ----------------
__device__ __forceinline__ uint32_t cvt_bf16x2(float lo_elem, float hi_elem) {
    uint32_t r;
    asm("cvt.rn.bf16x2.f32 %0, %1, %2;" : "=r"(r) : "f"(hi_elem), "f"(lo_elem));
    return r;
}
__device__ __forceinline__ void split2(float a, float b, uint32_t& h, uint32_t& l) {
    h = cvt_bf16x2(a, b);
    float ha = __uint_as_float(h << 16);
    float hb = __uint_as_float(h & 0xffff0000u);
    l = cvt_bf16x2(a - ha, b - hb);
}
__device__ __forceinline__ float2 bf2f(uint32_t u) {
    __nv_bfloat162 h = *(__nv_bfloat162*)&u;
    return make_float2(__bfloat162float(h.x), __bfloat162float(h.y));
}
__device__ __forceinline__ void ldsm4(uint32_t addr, uint32_t& r0, uint32_t& r1,
                                      uint32_t& r2, uint32_t& r3) {
    asm volatile("ldmatrix.sync.aligned.m8n8.x4.shared.b16 {%0,%1,%2,%3}, [%4];"
                 : "=r"(r0), "=r"(r1), "=r"(r2), "=r"(r3) : "r"(addr));
}
__device__ __forceinline__ void ldsm4t(uint32_t addr, uint32_t& r0, uint32_t& r1,
                                       uint32_t& r2, uint32_t& r3) {
    asm volatile("ldmatrix.sync.aligned.m8n8.x4.trans.shared.b16 {%0,%1,%2,%3}, [%4];"
                 : "=r"(r0), "=r"(r1), "=r"(r2), "=r"(r3) : "r"(addr));
}
__device__ __forceinline__ void mma16816(float* c, const uint32_t* a, const uint32_t* b) {
    asm volatile(
        "mma.sync.aligned.m16n8k16.row.col.f32.bf16.bf16.f32 "
        "{%0,%1,%2,%3}, {%4,%5,%6,%7}, {%8,%9}, {%0,%1,%2,%3};"
        : "+f"(c[0]), "+f"(c[1]), "+f"(c[2]), "+f"(c[3])
        : "r"(a[0]), "r"(a[1]), "r"(a[2]), "r"(a[3]), "r"(b[0]), "r"(b[1]));
}

// ---------------- pack kernels ----------------
__global__ void pack_wei(const float* __restrict__ We, const float* __restrict__ Wi) {
    size_t i = (size_t)blockIdx.x * blockDim.x + threadIdx.x;
    const size_t total = (size_t)NLAY * DIM * 2 * DIM;
    if (i >= total) return;
    int l = (int)(i / ((size_t)DIM * 2 * DIM));
    size_t r = i % ((size_t)DIM * 2 * DIM);
    int k = (int)(r / (2 * DIM));
    int n = (int)(r % (2 * DIM));
    const float* src;
    int nn;
    if (n < DIM) { src = We; nn = n; } else { src = Wi; nn = n - DIM; }
    int m = nn / HW, h = nn % HW;
    float v = src[(((size_t)l * NMC + m) * DIM + k) * HW + h];
    __nv_bfloat16 hb = __float2bfloat16(v);
    g_w_h[OFF_WEI + i] = hb;
    g_w_l[OFF_WEI + i] = __float2bfloat16(v - __bfloat162float(hb));
}

__global__ void pack_split(const float* __restrict__ src, __nv_bfloat16* __restrict__ dh,
                           __nv_bfloat16* __restrict__ dl, size_t total) {
    size_t i = ((size_t)blockIdx.x * blockDim.x + threadIdx.x) * 4;
    if (i >= total) return;
    float4 v = *(const float4*)(src + i);
    uint32_t h0, l0, h1, l1;
    split2(v.x, v.y, h0, l0);
    split2(v.z, v.w, h1, l1);
    *(uint2*)(dh + i) = make_uint2(h0, h1);
    *(uint2*)(dl + i) = make_uint2(l0, l1);
}

__global__ void pack_bias_kernel(const float* __restrict__ be, const float* __restrict__ bi) {
    int i = blockIdx.x * blockDim.x + threadIdx.x;
    if (i >= NLAY * 2 * DIM) return;
    int l = i / (2 * DIM);
    int n = i % (2 * DIM);
    g_bei[i] = (n < DIM) ? be[l * DIM + n] : bi[l * DIM + (n - DIM)];
}

// ---------------- bf16x3 HMMA GEMM, register-staged double buffer ----------------
// C[128x128/CTA] = epi( A[M,1024] @ W[1024,N] + bias ), A/W pre-split bf16 hi/lo.
// EPI 0: split only  1: relu+split  2: fp32 out + split  3: fp32 out += + split
template <int EPI>
__global__ __launch_bounds__(256, 1)
void bgemm(const __nv_bfloat16* __restrict__ Ah, const __nv_bfloat16* __restrict__ Al,
           const __nv_bfloat16* __restrict__ Wh, const __nv_bfloat16* __restrict__ Wl,
           const float* __restrict__ bias,
           __nv_bfloat16* __restrict__ oHi, __nv_bfloat16* __restrict__ oLo,
           float* __restrict__ oF, int N) {
    extern __shared__ __nv_bfloat16 smem[];
    __nv_bfloat16* sAh = smem;                      // [2][BM][AST]
    __nv_bfloat16* sAl = sAh + 2 * BM * AST;
    __nv_bfloat16* sWh = sAl + 2 * BM * AST;        // [2][BK][WST]
    __nv_bfloat16* sWl = sWh + 2 * BK * WST;
    const uint32_t sAh_u = (uint32_t)__cvta_generic_to_shared(sAh);
    const uint32_t sAl_u = (uint32_t)__cvta_generic_to_shared(sAl);
    const uint32_t sWh_u = (uint32_t)__cvta_generic_to_shared(sWh);
    const uint32_t sWl_u = (uint32_t)__cvta_generic_to_shared(sWl);

    const int tid = threadIdx.x;
    const int lane = tid & 31, wid = tid >> 5;
    const int wm = wid >> 2, wn = wid & 3;          // warp grid 2 (M) x 4 (N)
    const int bx = blockIdx.x, by = blockIdx.y;

    const char* pAh = (const char*)Ah + (size_t)by * BM * (DIM * 2);
    const char* pAl = (const char*)Al + (size_t)by * BM * (DIM * 2);
    const char* pWh = (const char*)Wh + (size_t)bx * BN * 2;
    const char* pWl = (const char*)Wl + (size_t)bx * BN * 2;
    const size_t wrow_b = (size_t)N * 2;

    // loader mappings (per i=0..1)
    int aR[2], aC[2], wR[2], wC[2];
    size_t gA[2], gW[2];
    int sA[2], sW[2];
#pragma unroll
    for (int i = 0; i < 2; i++) {
        int idx = i * 256 + tid;
        aR[i] = idx >> 2; aC[i] = idx & 3;                 // A: 128 rows x 4x16B
        gA[i] = (size_t)aR[i] * (DIM * 2) + (size_t)aC[i] * 16;
        sA[i] = aR[i] * AST + aC[i] * 8;
        wR[i] = idx >> 4; wC[i] = idx & 15;                // W: 32 rows x 16x16B
        gW[i] = (size_t)wR[i] * wrow_b + (size_t)wC[i] * 16;
        sW[i] = wR[i] * WST + wC[i] * 8;
    }

    float acc[4][4][4];
#pragma unroll
    for (int mt = 0; mt < 4; mt++)
#pragma unroll
        for (int nt = 0; nt < 4; nt++)
#pragma unroll
            for (int q = 0; q < 4; q++) acc[mt][nt][q] = 0.f;

    uint4 ra_h[2], ra_l[2], rw_h[2], rw_l[2];

    // prologue: chunk 0
#pragma unroll
    for (int i = 0; i < 2; i++) {
        ra_h[i] = *(const uint4*)(pAh + gA[i]);
        ra_l[i] = *(const uint4*)(pAl + gA[i]);
        rw_h[i] = *(const uint4*)(pWh + gW[i]);
        rw_l[i] = *(const uint4*)(pWl + gW[i]);
    }
#pragma unroll
    for (int i = 0; i < 2; i++) {
        *(uint4*)(sAh + sA[i]) = ra_h[i];
        *(uint4*)(sAl + sA[i]) = ra_l[i];
        *(uint4*)(sWh + sW[i]) = rw_h[i];
        *(uint4*)(sWl + sW[i]) = rw_l[i];
    }
    __syncthreads();

    const int lrow = lane & 15;
    const int lcol8 = (lane >> 4) * 8;

    for (int t = 0; t < NTCH; t++) {
        const int cur = t & 1;
        if (t + 1 < NTCH) {
            const size_t cbA = (size_t)(t + 1) * (BK * 2);
            const size_t cbW = (size_t)(t + 1) * BK * wrow_b;
#pragma unroll
            for (int i = 0; i < 2; i++) {
                ra_h[i] = *(const uint4*)(pAh + gA[i] + cbA);
                ra_l[i] = *(const uint4*)(pAl + gA[i] + cbA);
                rw_h[i] = *(const uint4*)(pWh + gW[i] + cbW);
                rw_l[i] = *(const uint4*)(pWl + gW[i] + cbW);
            }
        }

#pragma unroll
        for (int ks = 0; ks < 2; ks++) {
            uint32_t ah[4][4], al[4][4], bh[4][2], bl[4][2];
#pragma unroll
            for (int mt = 0; mt < 4; mt++) {
                uint32_t off = (uint32_t)((cur * BM + wm * 64 + mt * 16 + lrow) * AST +
                                          ks * 16 + lcol8) * 2;
                ldsm4(sAh_u + off, ah[mt][0], ah[mt][1], ah[mt][2], ah[mt][3]);
                ldsm4(sAl_u + off, al[mt][0], al[mt][1], al[mt][2], al[mt][3]);
            }
#pragma unroll
            for (int np = 0; np < 2; np++) {
                uint32_t off = (uint32_t)((cur * BK + ks * 16 + lrow) * WST +
                                          wn * 32 + np * 16 + lcol8) * 2;
                uint32_t r0, r1, r2, r3;
                ldsm4t(sWh_u + off, r0, r1, r2, r3);
                bh[np * 2][0] = r0; bh[np * 2][1] = r1;
                bh[np * 2 + 1][0] = r2; bh[np * 2 + 1][1] = r3;
                ldsm4t(sWl_u + off, r0, r1, r2, r3);
                bl[np * 2][0] = r0; bl[np * 2][1] = r1;
                bl[np * 2 + 1][0] = r2; bl[np * 2 + 1][1] = r3;
            }
#pragma unroll
            for (int mt = 0; mt < 4; mt++)
#pragma unroll
                for (int nt = 0; nt < 4; nt++) mma16816(acc[mt][nt], ah[mt], bh[nt]);
#pragma unroll
            for (int mt = 0; mt < 4; mt++)
#pragma unroll
                for (int nt = 0; nt < 4; nt++) mma16816(acc[mt][nt], ah[mt], bl[nt]);
#pragma unroll
            for (int mt = 0; mt < 4; mt++)
#pragma unroll
                for (int nt = 0; nt < 4; nt++) mma16816(acc[mt][nt], al[mt], bh[nt]);
        }

        if (t + 1 < NTCH) {
            const int nxt = cur ^ 1;
#pragma unroll
            for (int i = 0; i < 2; i++) {
                *(uint4*)(sAh + nxt * BM * AST + sA[i]) = ra_h[i];
                *(uint4*)(sAl + nxt * BM * AST + sA[i]) = ra_l[i];
                *(uint4*)(sWh + nxt * BK * WST + sW[i]) = rw_h[i];
                *(uint4*)(sWl + nxt * BK * WST + sW[i]) = rw_l[i];
            }
            __syncthreads();
        }
    }

    // ---------------- epilogue ----------------
    const int g = lane >> 2;
    const int tg = lane & 3;
#pragma unroll
    for (int mt = 0; mt < 4; mt++) {
        const int r0 = by * BM + wm * 64 + mt * 16 + g;
#pragma unroll
        for (int nt = 0; nt < 4; nt++) {
            const int col = bx * BN + wn * 32 + nt * 8 + tg * 2;
            float2 bv = *(const float2*)(bias + col);
            float2 v0, v1;
            v0.x = acc[mt][nt][0] + bv.x;  v0.y = acc[mt][nt][1] + bv.y;
            v1.x = acc[mt][nt][2] + bv.x;  v1.y = acc[mt][nt][3] + bv.y;
            if (EPI == 1) {
                v0.x = fmaxf(v0.x, 0.f); v0.y = fmaxf(v0.y, 0.f);
                v1.x = fmaxf(v1.x, 0.f); v1.y = fmaxf(v1.y, 0.f);
            }
            if (EPI >= 2) {
                float* p0 = oF + (size_t)r0 * N + col;
                float* p1 = oF + (size_t)(r0 + 8) * N + col;
                if (EPI == 3) {
                    float2 o0 = *(const float2*)p0;
                    float2 o1 = *(const float2*)p1;
                    v0.x += o0.x; v0.y += o0.y; v1.x += o1.x; v1.y += o1.y;
                }
                *(float2*)p0 = v0;
                *(float2*)p1 = v1;
            }
            uint32_t h0, l0, h1, l1;
            split2(v0.x, v0.y, h0, l0);
            split2(v1.x, v1.y, h1, l1);
            *(uint32_t*)(oHi + (size_t)r0 * N + col)       = h0;
            *(uint32_t*)(oLo + (size_t)r0 * N + col)       = l0;
            *(uint32_t*)(oHi + (size_t)(r0 + 8) * N + col) = h1;
            *(uint32_t*)(oLo + (size_t)(r0 + 8) * N + col) = l1;
        }
    }
}

// ---------------- minicolumn block-diag (bf16 hi/lo IO) ----------------
__global__ __launch_bounds__(256)
void mc_kernel(const __nv_bfloat16* __restrict__ eH, const __nv_bfloat16* __restrict__ eL,
               const float* __restrict__ Wl, const float* __restrict__ bl,
               __nv_bfloat16* __restrict__ mH, __nv_bfloat16* __restrict__ mL) {
    __shared__ float sW[HW * HW];
    __shared__ float sb[HW];
    const int m = blockIdx.y;
    if (threadIdx.x < HW * HW) sW[threadIdx.x] = Wl[m * HW * HW + threadIdx.x];
    if (threadIdx.x < HW)      sb[threadIdx.x] = bl[m * HW + threadIdx.x];
    __syncthreads();

    const int b = blockIdx.x * 256 + threadIdx.x;
    const size_t base = (size_t)b * (2 * DIM);

    float exc[HW], inh[HW];
#pragma unroll
    for (int part = 0; part < 2; part++) {
        size_t off = base + (part ? DIM : 0) + m * HW;
        uint4 hA = *(const uint4*)(eH + off);
        uint4 hB = *(const uint4*)(eH + off + 8);
        uint4 lA = *(const uint4*)(eL + off);
        uint4 lB = *(const uint4*)(eL + off + 8);
        uint32_t hw_[4] = {hA.x, hA.y, hA.z, hA.w};
        uint32_t hw2[4] = {hB.x, hB.y, hB.z, hB.w};
        uint32_t lw_[4] = {lA.x, lA.y, lA.z, lA.w};
        uint32_t lw2[4] = {lB.x, lB.y, lB.z, lB.w};
        float* dst = part ? inh : exc;
#pragma unroll
        for (int j = 0; j < 4; j++) {
            float2 h2 = bf2f(hw_[j]); float2 l2 = bf2f(lw_[j]);
            dst[j * 2 + 0] = h2.x + l2.x;
            dst[j * 2 + 1] = h2.y + l2.y;
            float2 h3 = bf2f(hw2[j]); float2 l3 = bf2f(lw2[j]);
            dst[8 + j * 2 + 0] = h3.x + l3.x;
            dst[8 + j * 2 + 1] = h3.y + l3.y;
        }
    }

    float out[HW];
#pragma unroll
    for (int k = 0; k < HW; k++) {
        float lat = sb[k];
#pragma unroll
        for (int h = 0; h < HW; h++) lat += inh[h] * sW[h * HW + k];
        out[k] = fmaxf(exc[k] - lat, 0.f);
    }

    uint32_t hu[8], lu[8];
#pragma unroll
    for (int p = 0; p < 8; p++) split2(out[2 * p], out[2 * p + 1], hu[p], lu[p]);
    size_t o = (size_t)b * DIM + m * HW;
    *(uint4*)(mH + o)     = make_uint4(hu[0], hu[1], hu[2], hu[3]);
    *(uint4*)(mH + o + 8) = make_uint4(hu[4], hu[5], hu[6], hu[7]);
    *(uint4*)(mL + o)     = make_uint4(lu[0], lu[1], lu[2], lu[3]);
    *(uint4*)(mL + o + 8) = make_uint4(lu[4], lu[5], lu[6], lu[7]);
}

// ---------------- driver ----------------
extern "C" void kernel_launch(void* const* d_in, const int* in_sizes, int n_in,
                              void* d_out, int out_size) {
    const float* x    = (const float*)d_in[0];
    const float* We   = (const float*)d_in[1];
    const float* be   = (const float*)d_in[2];
    const float* Wi   = (const float*)d_in[3];
    const float* bi   = (const float*)d_in[4];
    const float* Wl   = (const float*)d_in[5];
    const float* bl   = (const float*)d_in[6];
    const float* Wlat = (const float*)d_in[7];
    const float* blat = (const float*)d_in[8];
    const float* Wv   = (const float*)d_in[9];
    const float* bv   = (const float*)d_in[10];
    const float* Wo   = (const float*)d_in[11];
    const float* bo   = (const float*)d_in[12];
    const float* fbW  = (const float*)d_in[13];
    const float* fbb  = (const float*)d_in[14];
    float* out = (float*)d_out;

    const size_t BD = (size_t)BATCH * DIM;

    __nv_bfloat16 *w_h, *w_l, *actA_h, *actA_l, *actB_h, *actB_l;
    __nv_bfloat16 *ei_h, *ei_l, *mc_h, *mc_l, *lat_h, *lat_l;
    float* bei_p;
    cudaGetSymbolAddress((void**)&w_h, g_w_h);
    cudaGetSymbolAddress((void**)&w_l, g_w_l);
    cudaGetSymbolAddress((void**)&actA_h, g_actA_h);
    cudaGetSymbolAddress((void**)&actA_l, g_actA_l);
    cudaGetSymbolAddress((void**)&actB_h, g_actB_h);
    cudaGetSymbolAddress((void**)&actB_l, g_actB_l);
    cudaGetSymbolAddress((void**)&ei_h, g_ei_h);
    cudaGetSymbolAddress((void**)&ei_l, g_ei_l);
    cudaGetSymbolAddress((void**)&mc_h, g_mc_h);
    cudaGetSymbolAddress((void**)&mc_l, g_mc_l);
    cudaGetSymbolAddress((void**)&lat_h, g_lat_h);
    cudaGetSymbolAddress((void**)&lat_l, g_lat_l);
    cudaGetSymbolAddress((void**)&bei_p, g_bei);

    cudaFuncSetAttribute(bgemm<0>, cudaFuncAttributeMaxDynamicSharedMemorySize, SMEM_BYTES);
    cudaFuncSetAttribute(bgemm<1>, cudaFuncAttributeMaxDynamicSharedMemorySize, SMEM_BYTES);
    cudaFuncSetAttribute(bgemm<2>, cudaFuncAttributeMaxDynamicSharedMemorySize, SMEM_BYTES);
    cudaFuncSetAttribute(bgemm<3>, cudaFuncAttributeMaxDynamicSharedMemorySize, SMEM_BYTES);

    // ---- packs ----
    {
        size_t tw = (size_t)NLAY * DIM * 2 * DIM;
        pack_wei<<<(unsigned)((tw + 255) / 256), 256>>>(We, Wi);
        pack_split<<<(unsigned)(6 * SQ / 4 / 256), 256>>>(Wlat, w_h + OFF_LAT, w_l + OFF_LAT, 6 * SQ);
        pack_split<<<(unsigned)(6 * SQ / 4 / 256), 256>>>(Wv,   w_h + OFF_V,   w_l + OFF_V,   6 * SQ);
        pack_split<<<(unsigned)(6 * SQ / 4 / 256), 256>>>(Wo,   w_h + OFF_O,   w_l + OFF_O,   6 * SQ);
        pack_split<<<(unsigned)(5 * SQ / 4 / 256), 256>>>(fbW,  w_h + OFF_FB,  w_l + OFF_FB,  5 * SQ);
        pack_split<<<(unsigned)(BD / 4 / 256), 256>>>(x, actA_h, actA_l, BD);
        pack_bias_kernel<<<(NLAY * 2 * DIM + 255) / 256, 256>>>(be, bi);
    }

    dim3 blk(256);
    dim3 grid_wide(2 * DIM / BN, BATCH / BM);
    dim3 grid_sq(DIM / BN, BATCH / BM);
    dim3 grid_mc(BATCH / 256, NMC);

    for (int l = 0; l < NLAY; l++) {
        const size_t weOff = OFF_WEI + (size_t)l * 2048 * 1024;
        // exc|inh = relu(act @ Wei + bei)
        bgemm<1><<<grid_wide, blk, SMEM_BYTES>>>(actA_h, actA_l, w_h + weOff, w_l + weOff,
                                                 bei_p + l * 2048, ei_h, ei_l, nullptr, 2048);
        // mc = relu(exc - (inh @ Wl + bl))
        mc_kernel<<<grid_mc, blk>>>(ei_h, ei_l, Wl + (size_t)l * NMC * HW * HW,
                                    bl + (size_t)l * NMC * HW, mc_h, mc_l);
        // lateral = mc @ Wlat + blat
        bgemm<0><<<grid_sq, blk, SMEM_BYTES>>>(mc_h, mc_l, w_h + OFF_LAT + (size_t)l * SQ,
                                               w_l + OFF_LAT + (size_t)l * SQ,
                                               blat + (size_t)l * DIM, lat_h, lat_l, nullptr, 1024);
        // tmp = lateral @ Wv + bv
        bgemm<0><<<grid_sq, blk, SMEM_BYTES>>>(lat_h, lat_l, w_h + OFF_V + (size_t)l * SQ,
                                               w_l + OFF_V + (size_t)l * SQ,
                                               bv + (size_t)l * DIM, mc_h, mc_l, nullptr, 1024);
        // attended = tmp @ Wo + bo -> out[l] fp32 + next-layer act split
        bgemm<2><<<grid_sq, blk, SMEM_BYTES>>>(mc_h, mc_l, w_h + OFF_O + (size_t)l * SQ,
                                               w_l + OFF_O + (size_t)l * SQ,
                                               bo + (size_t)l * DIM, actA_h, actA_l,
                                               out + (size_t)l * BD, 1024);
    }

    // feedback: out[idx] += fb_in @ fbW[i] + fbb[i]; fb_in hi/lo ping-pongs
    __nv_bfloat16 *fin_h = actA_h, *fin_l = actA_l, *fout_h = actB_h, *fout_l = actB_l;
    for (int i = 0; i < NLAY - 1; i++) {
        int idx = NLAY - 2 - i;
        bgemm<3><<<grid_sq, blk, SMEM_BYTES>>>(fin_h, fin_l, w_h + OFF_FB + (size_t)i * SQ,
                                               w_l + OFF_FB + (size_t)i * SQ,
                                               fbb + (size_t)i * DIM, fout_h, fout_l,
                                               out + (size_t)idx * BD, 1024);
        __nv_bfloat16* t;
        t = fin_h; fin_h = fout_h; fout_h = t;
        t = fin_l; fin_l = fout_l; fout_l = t;
    }
}

// round 7
// speedup vs baseline: 1.3680x; 1.1498x over previous
#include <cuda_runtime.h>
#include <cuda_bf16.h>
#include <cstdint>

#define BATCH 16384
#define DIM   1024
#define NLAY  6
#define NMC   64
#define HW    16

#define BM 128
#define BN 128
#define BK 32
#define AST 40     // A smem row stride (bf16 elems)
#define WST 136    // W smem row stride (bf16 elems)
#define NTCH (DIM / BK)   // 32 K-chunks

#define SMEM_BYTES ((2 * BM * AST * 2 + 2 * BK * WST * 2) * 2)  // 75776
// fused-mc epilogue smem layout (fp32 view of same buffer):
#define TSTR 132                        // tile row stride (floats)
#define TILE_F (128 * TSTR)             // 67584 floats? -> bytes = 67584*... (128*132*4 = 67584 B)
#define SWL_OFF (128 * TSTR)            // float index of Wl block
#define SBL_OFF (SWL_OFF + 4 * 256)     // float index of bl block

// ---------------- static device scratch ----------------
#define SQ ((size_t)1048576)
#define OFF_WEI ((size_t)0)
#define OFF_LAT ((size_t)(6 * 2048 * 1024))
#define OFF_V   (OFF_LAT + 6 * SQ)
#define OFF_O   (OFF_V + 6 * SQ)
#define OFF_FB  (OFF_O + 6 * SQ)
#define OFF_VO  (OFF_FB + 5 * SQ)
#define WT_TOT  (OFF_VO + 6 * SQ)

__device__ __nv_bfloat16 g_w_h[WT_TOT];
__device__ __nv_bfloat16 g_w_l[WT_TOT];
__device__ float g_bei[NLAY * 2 * DIM];   // interleaved [mc][exc16|inh16]
__device__ float g_bvo[NLAY * DIM];

__device__ __nv_bfloat16 g_actA_h[(size_t)BATCH * DIM];
__device__ __nv_bfloat16 g_actA_l[(size_t)BATCH * DIM];
__device__ __nv_bfloat16 g_actB_h[(size_t)BATCH * DIM];
__device__ __nv_bfloat16 g_actB_l[(size_t)BATCH * DIM];
__device__ __nv_bfloat16 g_mc_h[(size_t)BATCH * DIM];
__device__ __nv_bfloat16 g_mc_l[(size_t)BATCH * DIM];
__device__ __nv_bfloat16 g_lat_h[(size_t)BATCH * DIM];
__device__ __nv_bfloat16 g_lat_l[(size_t)BATCH * DIM];

// ---------------- helpers ----------------
__device__ __forceinline__ uint32_t cvt_bf16x2(float lo_elem, float hi_elem) {
    uint32_t r;
    asm("cvt.rn.bf16x2.f32 %0, %1, %2;" : "=r"(r) : "f"(hi_elem), "f"(lo_elem));
    return r;
}
__device__ __forceinline__ void split2(float a, float b, uint32_t& h, uint32_t& l) {
    h = cvt_bf16x2(a, b);
    float ha = __uint_as_float(h << 16);
    float hb = __uint_as_float(h & 0xffff0000u);
    l = cvt_bf16x2(a - ha, b - hb);
}
__device__ __forceinline__ void ldsm4(uint32_t addr, uint32_t& r0, uint32_t& r1,
                                      uint32_t& r2, uint32_t& r3) {
    asm volatile("ldmatrix.sync.aligned.m8n8.x4.shared.b16 {%0,%1,%2,%3}, [%4];"
                 : "=r"(r0), "=r"(r1), "=r"(r2), "=r"(r3) : "r"(addr));
}
__device__ __forceinline__ void ldsm4t(uint32_t addr, uint32_t& r0, uint32_t& r1,
                                       uint32_t& r2, uint32_t& r3) {
    asm volatile("ldmatrix.sync.aligned.m8n8.x4.trans.shared.b16 {%0,%1,%2,%3}, [%4];"
                 : "=r"(r0), "=r"(r1), "=r"(r2), "=r"(r3) : "r"(addr));
}
__device__ __forceinline__ void mma16816(float* c, const uint32_t* a, const uint32_t* b) {
    asm volatile(
        "mma.sync.aligned.m16n8k16.row.col.f32.bf16.bf16.f32 "
        "{%0,%1,%2,%3}, {%4,%5,%6,%7}, {%8,%9}, {%0,%1,%2,%3};"
        : "+f"(c[0]), "+f"(c[1]), "+f"(c[2]), "+f"(c[3])
        : "r"(a[0]), "r"(a[1]), "r"(a[2]), "r"(a[3]), "r"(b[0]), "r"(b[1]));
}

// ---------------- pack kernels ----------------
// Interleaved fused Wei: output col n' -> mc = n'>>5, r = n'&31; r<16: We[h=r], else Wi[h=r-16]
__global__ void pack_wei(const float* __restrict__ We, const float* __restrict__ Wi) {
    size_t i = (size_t)blockIdx.x * blockDim.x + threadIdx.x;
    const size_t total = (size_t)NLAY * DIM * 2 * DIM;
    if (i >= total) return;
    int l = (int)(i / ((size_t)DIM * 2 * DIM));
    size_t r = i % ((size_t)DIM * 2 * DIM);
    int k = (int)(r / (2 * DIM));
    int n = (int)(r % (2 * DIM));
    int mc = n >> 5, rr = n & 31;
    const float* src;
    int h;
    if (rr < 16) { src = We; h = rr; } else { src = Wi; h = rr - 16; }
    float v = src[(((size_t)l * NMC + mc) * DIM + k) * HW + h];
    __nv_bfloat16 hb = __float2bfloat16(v);
    g_w_h[OFF_WEI + i] = hb;
    g_w_l[OFF_WEI + i] = __float2bfloat16(v - __bfloat162float(hb));
}

__global__ void pack_split(const float* __restrict__ src, __nv_bfloat16* __restrict__ dh,
                           __nv_bfloat16* __restrict__ dl, size_t total) {
    size_t i = ((size_t)blockIdx.x * blockDim.x + threadIdx.x) * 4;
    if (i >= total) return;
    float4 v = *(const float4*)(src + i);
    uint32_t h0, l0, h1, l1;
    split2(v.x, v.y, h0, l0);
    split2(v.z, v.w, h1, l1);
    *(uint2*)(dh + i) = make_uint2(h0, h1);
    *(uint2*)(dl + i) = make_uint2(l0, l1);
}

__global__ void pack_bias_kernel(const float* __restrict__ be, const float* __restrict__ bi) {
    int i = blockIdx.x * blockDim.x + threadIdx.x;
    if (i >= NLAY * 2 * DIM) return;
    int l = i / (2 * DIM);
    int n = i % (2 * DIM);
    int mc = n >> 5, rr = n & 31;
    g_bei[i] = (rr < 16) ? be[l * DIM + mc * HW + rr] : bi[l * DIM + mc * HW + (rr - 16)];
}

// bvo[l][n] = bv[l] @ Wo[l] [:,n] + bo[l][n]
__global__ void bvo_kernel(const float* __restrict__ bv, const float* __restrict__ Wo,
                           const float* __restrict__ bo) {
    int l = blockIdx.y;
    int n = blockIdx.x * 256 + threadIdx.x;
    const float* w = Wo + (size_t)l * SQ + n;
    const float* b = bv + l * DIM;
    float s = bo[l * DIM + n];
    for (int k = 0; k < DIM; k++) s += b[k] * w[(size_t)k * DIM];
    g_bvo[l * DIM + n] = s;
}

// ---------------- bf16x3 HMMA GEMM, register-staged double buffer ----------------
// EPI 0: bias + hi/lo split out
// EPI 1: fused minicolumn epilogue (wide GEMM): relu, block-diag lat, mc out
// EPI 2: bias + fp32 out + split      EPI 3: bias + fp32 out += + split
// BATCH6: 6 contiguous matrices; l = by>>3 selects W (A/out contiguous)
template <int EPI, bool BATCH6>
__global__ __launch_bounds__(256, 1)
void bgemm(const __nv_bfloat16* __restrict__ Ah, const __nv_bfloat16* __restrict__ Al,
           const __nv_bfloat16* __restrict__ Wh, const __nv_bfloat16* __restrict__ Wl,
           const float* __restrict__ bias,
           __nv_bfloat16* __restrict__ oHi, __nv_bfloat16* __restrict__ oLo,
           float* __restrict__ oF, int N,
           const float* __restrict__ mcW, const float* __restrict__ mcB) {
    extern __shared__ __nv_bfloat16 smem[];
    __nv_bfloat16* sAh = smem;
    __nv_bfloat16* sAl = sAh + 2 * BM * AST;
    __nv_bfloat16* sWh = sAl + 2 * BM * AST;
    __nv_bfloat16* sWl = sWh + 2 * BK * WST;
    const uint32_t sAh_u = (uint32_t)__cvta_generic_to_shared(sAh);
    const uint32_t sAl_u = (uint32_t)__cvta_generic_to_shared(sAl);
    const uint32_t sWh_u = (uint32_t)__cvta_generic_to_shared(sWh);
    const uint32_t sWl_u = (uint32_t)__cvta_generic_to_shared(sWl);

    const int tid = threadIdx.x;
    const int lane = tid & 31, wid = tid >> 5;
    const int wm = wid >> 2, wn = wid & 3;
    const int bx = blockIdx.x, by = blockIdx.y;

    if (BATCH6) {
        size_t ws = (size_t)(by >> 3) * SQ;
        Wh += ws; Wl += ws;
    }

    const char* pAh = (const char*)Ah + (size_t)by * BM * (DIM * 2);
    const char* pAl = (const char*)Al + (size_t)by * BM * (DIM * 2);
    const char* pWh = (const char*)Wh + (size_t)bx * BN * 2;
    const char* pWl = (const char*)Wl + (size_t)bx * BN * 2;
    const size_t wrow_b = (size_t)N * 2;

    int sA[2], sW[2];
    size_t gA[2], gW[2];
#pragma unroll
    for (int i = 0; i < 2; i++) {
        int idx = i * 256 + tid;
        int ar = idx >> 2, ac = idx & 3;
        gA[i] = (size_t)ar * (DIM * 2) + (size_t)ac * 16;
        sA[i] = ar * AST + ac * 8;
        int wr = idx >> 4, wc = idx & 15;
        gW[i] = (size_t)wr * wrow_b + (size_t)wc * 16;
        sW[i] = wr * WST + wc * 8;
    }

    float acc[4][4][4];
#pragma unroll
    for (int mt = 0; mt < 4; mt++)
#pragma unroll
        for (int nt = 0; nt < 4; nt++)
#pragma unroll
            for (int q = 0; q < 4; q++) acc[mt][nt][q] = 0.f;

    uint4 ra_h[2], ra_l[2], rw_h[2], rw_l[2];
#pragma unroll
    for (int i = 0; i < 2; i++) {
        ra_h[i] = *(const uint4*)(pAh + gA[i]);
        ra_l[i] = *(const uint4*)(pAl + gA[i]);
        rw_h[i] = *(const uint4*)(pWh + gW[i]);
        rw_l[i] = *(const uint4*)(pWl + gW[i]);
    }
#pragma unroll
    for (int i = 0; i < 2; i++) {
        *(uint4*)(sAh + sA[i]) = ra_h[i];
        *(uint4*)(sAl + sA[i]) = ra_l[i];
        *(uint4*)(sWh + sW[i]) = rw_h[i];
        *(uint4*)(sWl + sW[i]) = rw_l[i];
    }
    __syncthreads();

    const int lrow = lane & 15;
    const int lcol8 = (lane >> 4) * 8;

    for (int t = 0; t < NTCH; t++) {
        const int cur = t & 1;
        if (t + 1 < NTCH) {
            const size_t cbA = (size_t)(t + 1) * (BK * 2);
            const size_t cbW = (size_t)(t + 1) * BK * wrow_b;
#pragma unroll
            for (int i = 0; i < 2; i++) {
                ra_h[i] = *(const uint4*)(pAh + gA[i] + cbA);
                ra_l[i] = *(const uint4*)(pAl + gA[i] + cbA);
                rw_h[i] = *(const uint4*)(pWh + gW[i] + cbW);
                rw_l[i] = *(const uint4*)(pWl + gW[i] + cbW);
            }
        }

#pragma unroll
        for (int ks = 0; ks < 2; ks++) {
            uint32_t ah[4][4], al[4][4], bh[4][2], bl[4][2];
#pragma unroll
            for (int mt = 0; mt < 4; mt++) {
                uint32_t off = (uint32_t)((cur * BM + wm * 64 + mt * 16 + lrow) * AST +
                                          ks * 16 + lcol8) * 2;
                ldsm4(sAh_u + off, ah[mt][0], ah[mt][1], ah[mt][2], ah[mt][3]);
                ldsm4(sAl_u + off, al[mt][0], al[mt][1], al[mt][2], al[mt][3]);
            }
#pragma unroll
            for (int np = 0; np < 2; np++) {
                uint32_t off = (uint32_t)((cur * BK + ks * 16 + lrow) * WST +
                                          wn * 32 + np * 16 + lcol8) * 2;
                uint32_t r0, r1, r2, r3;
                ldsm4t(sWh_u + off, r0, r1, r2, r3);
                bh[np * 2][0] = r0; bh[np * 2][1] = r1;
                bh[np * 2 + 1][0] = r2; bh[np * 2 + 1][1] = r3;
                ldsm4t(sWl_u + off, r0, r1, r2, r3);
                bl[np * 2][0] = r0; bl[np * 2][1] = r1;
                bl[np * 2 + 1][0] = r2; bl[np * 2 + 1][1] = r3;
            }
#pragma unroll
            for (int mt = 0; mt < 4; mt++)
#pragma unroll
                for (int nt = 0; nt < 4; nt++) mma16816(acc[mt][nt], ah[mt], bh[nt]);
#pragma unroll
            for (int mt = 0; mt < 4; mt++)
#pragma unroll
                for (int nt = 0; nt < 4; nt++) mma16816(acc[mt][nt], ah[mt], bl[nt]);
#pragma unroll
            for (int mt = 0; mt < 4; mt++)
#pragma unroll
                for (int nt = 0; nt < 4; nt++) mma16816(acc[mt][nt], al[mt], bh[nt]);
        }

        if (t + 1 < NTCH) {
            const int nxt = cur ^ 1;
#pragma unroll
            for (int i = 0; i < 2; i++) {
                *(uint4*)(sAh + nxt * BM * AST + sA[i]) = ra_h[i];
                *(uint4*)(sAl + nxt * BM * AST + sA[i]) = ra_l[i];
                *(uint4*)(sWh + nxt * BK * WST + sW[i]) = rw_h[i];
                *(uint4*)(sWl + nxt * BK * WST + sW[i]) = rw_l[i];
            }
            __syncthreads();
        }
    }

    // ---------------- epilogue ----------------
    const int g = lane >> 2;
    const int tg = lane & 3;

    if (EPI == 1) {
        // fused minicolumn: stage relu'd exc|inh tile in smem, apply block-diag, emit mc
        float* tileF = (float*)smem;
        __syncthreads();   // mainloop smem reads done before overwrite
#pragma unroll
        for (int mt = 0; mt < 4; mt++) {
            const int rl = wm * 64 + mt * 16 + g;
#pragma unroll
            for (int nt = 0; nt < 4; nt++) {
                const int cl = wn * 32 + nt * 8 + tg * 2;
                float2 bv = *(const float2*)(bias + bx * BN + cl);
                tileF[rl * TSTR + cl]           = fmaxf(acc[mt][nt][0] + bv.x, 0.f);
                tileF[rl * TSTR + cl + 1]       = fmaxf(acc[mt][nt][1] + bv.y, 0.f);
                tileF[(rl + 8) * TSTR + cl]     = fmaxf(acc[mt][nt][2] + bv.x, 0.f);
                tileF[(rl + 8) * TSTR + cl + 1] = fmaxf(acc[mt][nt][3] + bv.y, 0.f);
            }
        }
        // load 4 minicolumns' Wl + bl
        float* sWlF = tileF + SWL_OFF;
        float* sblF = tileF + SBL_OFF;
#pragma unroll
        for (int i = 0; i < 4; i++) sWlF[i * 256 + tid] = mcW[(size_t)(bx * 4) * 256 + i * 256 + tid];
        if (tid < 64) sblF[tid] = mcB[bx * 64 + tid];
        __syncthreads();

#pragma unroll
        for (int it = 0; it < 2; it++) {
            int w = it * 256 + tid;
            int j = w & 3, row = w >> 2;     // j: local mc, row: 0..127
            const float* tr = tileF + row * TSTR + j * 32;
            float inh[16];
#pragma unroll
            for (int h = 0; h < 16; h++) inh[h] = tr[16 + h];
            float o[16];
#pragma unroll
            for (int k = 0; k < 16; k++) {
                float lat = sblF[j * 16 + k];
#pragma unroll
                for (int h = 0; h < 16; h++) lat += inh[h] * sWlF[j * 256 + h * 16 + k];
                o[k] = fmaxf(tr[k] - lat, 0.f);
            }
            uint32_t hu[8], lu[8];
#pragma unroll
            for (int p = 0; p < 8; p++) split2(o[2 * p], o[2 * p + 1], hu[p], lu[p]);
            size_t oo = (size_t)(by * 128 + row) * DIM + (bx * 4 + j) * 16;
            *(uint4*)(oHi + oo)     = make_uint4(hu[0], hu[1], hu[2], hu[3]);
            *(uint4*)(oHi + oo + 8) = make_uint4(hu[4], hu[5], hu[6], hu[7]);
            *(uint4*)(oLo + oo)     = make_uint4(lu[0], lu[1], lu[2], lu[3]);
            *(uint4*)(oLo + oo + 8) = make_uint4(lu[4], lu[5], lu[6], lu[7]);
        }
        return;
    }

#pragma unroll
    for (int mt = 0; mt < 4; mt++) {
        const int r0 = by * BM + wm * 64 + mt * 16 + g;
#pragma unroll
        for (int nt = 0; nt < 4; nt++) {
            const int col = bx * BN + wn * 32 + nt * 8 + tg * 2;
            float2 bv = bias ? *(const float2*)(bias + col) : make_float2(0.f, 0.f);
            float2 v0, v1;
            v0.x = acc[mt][nt][0] + bv.x;  v0.y = acc[mt][nt][1] + bv.y;
            v1.x = acc[mt][nt][2] + bv.x;  v1.y = acc[mt][nt][3] + bv.y;
            if (EPI >= 2) {
                float* p0 = oF + (size_t)r0 * N + col;
                float* p1 = oF + (size_t)(r0 + 8) * N + col;
                if (EPI == 3) {
                    float2 o0 = *(const float2*)p0;
                    float2 o1 = *(const float2*)p1;
                    v0.x += o0.x; v0.y += o0.y; v1.x += o1.x; v1.y += o1.y;
                }
                *(float2*)p0 = v0;
                *(float2*)p1 = v1;
            }
            uint32_t h0, l0, h1, l1;
            split2(v0.x, v0.y, h0, l0);
            split2(v1.x, v1.y, h1, l1);
            *(uint32_t*)(oHi + (size_t)r0 * N + col)       = h0;
            *(uint32_t*)(oLo + (size_t)r0 * N + col)       = l0;
            *(uint32_t*)(oHi + (size_t)(r0 + 8) * N + col) = h1;
            *(uint32_t*)(oLo + (size_t)(r0 + 8) * N + col) = l1;
        }
    }
}

// ---------------- driver ----------------
extern "C" void kernel_launch(void* const* d_in, const int* in_sizes, int n_in,
                              void* d_out, int out_size) {
    const float* x    = (const float*)d_in[0];
    const float* We   = (const float*)d_in[1];
    const float* be   = (const float*)d_in[2];
    const float* Wi   = (const float*)d_in[3];
    const float* bi   = (const float*)d_in[4];
    const float* Wl   = (const float*)d_in[5];
    const float* bl   = (const float*)d_in[6];
    const float* Wlat = (const float*)d_in[7];
    const float* blat = (const float*)d_in[8];
    const float* Wv   = (const float*)d_in[9];
    const float* bv   = (const float*)d_in[10];
    const float* Wo   = (const float*)d_in[11];
    const float* bo   = (const float*)d_in[12];
    const float* fbW  = (const float*)d_in[13];
    const float* fbb  = (const float*)d_in[14];
    float* out = (float*)d_out;

    const size_t BD = (size_t)BATCH * DIM;

    __nv_bfloat16 *w_h, *w_l, *actA_h, *actA_l, *actB_h, *actB_l;
    __nv_bfloat16 *mc_h, *mc_l, *lat_h, *lat_l;
    float *bei_p, *bvo_p;
    cudaGetSymbolAddress((void**)&w_h, g_w_h);
    cudaGetSymbolAddress((void**)&w_l, g_w_l);
    cudaGetSymbolAddress((void**)&actA_h, g_actA_h);
    cudaGetSymbolAddress((void**)&actA_l, g_actA_l);
    cudaGetSymbolAddress((void**)&actB_h, g_actB_h);
    cudaGetSymbolAddress((void**)&actB_l, g_actB_l);
    cudaGetSymbolAddress((void**)&mc_h, g_mc_h);
    cudaGetSymbolAddress((void**)&mc_l, g_mc_l);
    cudaGetSymbolAddress((void**)&lat_h, g_lat_h);
    cudaGetSymbolAddress((void**)&lat_l, g_lat_l);
    cudaGetSymbolAddress((void**)&bei_p, g_bei);
    cudaGetSymbolAddress((void**)&bvo_p, g_bvo);

    cudaFuncSetAttribute((const void*)bgemm<0, false>, cudaFuncAttributeMaxDynamicSharedMemorySize, SMEM_BYTES);
    cudaFuncSetAttribute((const void*)bgemm<0, true>,  cudaFuncAttributeMaxDynamicSharedMemorySize, SMEM_BYTES);
    cudaFuncSetAttribute((const void*)bgemm<1, false>, cudaFuncAttributeMaxDynamicSharedMemorySize, SMEM_BYTES);
    cudaFuncSetAttribute((const void*)bgemm<2, false>, cudaFuncAttributeMaxDynamicSharedMemorySize, SMEM_BYTES);
    cudaFuncSetAttribute((const void*)bgemm<3, false>, cudaFuncAttributeMaxDynamicSharedMemorySize, SMEM_BYTES);

    // ---- packs ----
    {
        size_t tw = (size_t)NLAY * DIM * 2 * DIM;
        pack_wei<<<(unsigned)((tw + 255) / 256), 256>>>(We, Wi);
        pack_split<<<(unsigned)(6 * SQ / 4 / 256), 256>>>(Wlat, w_h + OFF_LAT, w_l + OFF_LAT, 6 * SQ);
        pack_split<<<(unsigned)(6 * SQ / 4 / 256), 256>>>(Wv,   w_h + OFF_V,   w_l + OFF_V,   6 * SQ);
        pack_split<<<(unsigned)(6 * SQ / 4 / 256), 256>>>(Wo,   w_h + OFF_O,   w_l + OFF_O,   6 * SQ);
        pack_split<<<(unsigned)(5 * SQ / 4 / 256), 256>>>(fbW,  w_h + OFF_FB,  w_l + OFF_FB,  5 * SQ);
        pack_split<<<(unsigned)(BD / 4 / 256), 256>>>(x, actA_h, actA_l, BD);
        pack_bias_kernel<<<(NLAY * 2 * DIM + 255) / 256, 256>>>(be, bi);
        bvo_kernel<<<dim3(4, NLAY), 256>>>(bv, Wo, bo);
        // Wvo[l] = Wv[l] @ Wo[l], all 6 layers in one batched launch
        bgemm<0, true><<<dim3(8, 48), 256, SMEM_BYTES>>>(
            w_h + OFF_V, w_l + OFF_V, w_h + OFF_O, w_l + OFF_O, nullptr,
            w_h + OFF_VO, w_l + OFF_VO, nullptr, 1024, nullptr, nullptr);
    }

    dim3 blk(256);
    dim3 grid_wide(2 * DIM / BN, BATCH / BM);
    dim3 grid_sq(DIM / BN, BATCH / BM);

    for (int l = 0; l < NLAY; l++) {
        const size_t weOff = OFF_WEI + (size_t)l * 2048 * 1024;
        // fused: exc|inh GEMM + relu + minicolumn block-diag -> mc hi/lo
        bgemm<1, false><<<grid_wide, blk, SMEM_BYTES>>>(
            actA_h, actA_l, w_h + weOff, w_l + weOff, bei_p + l * 2048,
            mc_h, mc_l, nullptr, 2048,
            Wl + (size_t)l * NMC * HW * HW, bl + (size_t)l * NMC * HW);
        // lateral = mc @ Wlat + blat
        bgemm<0, false><<<grid_sq, blk, SMEM_BYTES>>>(
            mc_h, mc_l, w_h + OFF_LAT + (size_t)l * SQ, w_l + OFF_LAT + (size_t)l * SQ,
            blat + (size_t)l * DIM, lat_h, lat_l, nullptr, 1024, nullptr, nullptr);
        // attended = lateral @ Wvo + bvo -> out[l] fp32 + next act split
        bgemm<2, false><<<grid_sq, blk, SMEM_BYTES>>>(
            lat_h, lat_l, w_h + OFF_VO + (size_t)l * SQ, w_l + OFF_VO + (size_t)l * SQ,
            bvo_p + l * DIM, actA_h, actA_l, out + (size_t)l * BD, 1024, nullptr, nullptr);
    }

    // feedback: out[idx] += fb_in @ fbW[i] + fbb[i]
    __nv_bfloat16 *fin_h = actA_h, *fin_l = actA_l, *fout_h = actB_h, *fout_l = actB_l;
    for (int i = 0; i < NLAY - 1; i++) {
        int idx = NLAY - 2 - i;
        bgemm<3, false><<<grid_sq, blk, SMEM_BYTES>>>(
            fin_h, fin_l, w_h + OFF_FB + (size_t)i * SQ, w_l + OFF_FB + (size_t)i * SQ,
            fbb + (size_t)i * DIM, fout_h, fout_l, out + (size_t)idx * BD, 1024,
            nullptr, nullptr);
        __nv_bfloat16* t;
        t = fin_h; fin_h = fout_h; fout_h = t;
        t = fin_l; fin_l = fout_l; fout_l = t;
    }
}

// round 8
// speedup vs baseline: 1.6436x; 1.2014x over previous
#include <cuda_runtime.h>
#include <cuda_bf16.h>
#include <cstdint>

#define BATCH 16384
#define DIM   1024
#define NLAY  6
#define NMC   64
#define HW    16

#define BM 128
#define BN 128
#define BK 32
#define AST 40     // A smem row stride (bf16 elems)
#define WST 136    // W smem row stride (bf16 elems)
#define NTCH (DIM / BK)   // 32 K-chunks

#define SMEM_BYTES ((2 * BM * AST * 2 + 2 * BK * WST * 2) * 2)  // 75776
// fused-mc epilogue smem layout (fp32 view of same buffer):
#define TSTR 132
#define SWL_OFF (128 * TSTR)
#define SBL_OFF (SWL_OFF + 4 * 256)

// ---------------- static device scratch ----------------
#define SQ ((size_t)1048576)
#define OFF_WEI ((size_t)0)
#define OFF_LAT ((size_t)(6 * 2048 * 1024))
#define OFF_V   (OFF_LAT + 6 * SQ)
#define OFF_O   (OFF_V + 6 * SQ)
#define OFF_FB  (OFF_O + 6 * SQ)
#define OFF_VO  (OFF_FB + 5 * SQ)
#define OFF_W3  (OFF_VO + 6 * SQ)
#define WT_TOT  (OFF_W3 + 6 * SQ)

__device__ __nv_bfloat16 g_w_h[WT_TOT];
__device__ __nv_bfloat16 g_w_l[WT_TOT];
__device__ float g_bei[NLAY * 2 * DIM];   // interleaved [mc][exc16|inh16]
__device__ float g_bvo[NLAY * DIM];
__device__ float g_b3[NLAY * DIM];
__device__ float g_wvo_f[6 * SQ];         // fp32 Wvo (for exact b3)

__device__ __nv_bfloat16 g_actA_h[(size_t)BATCH * DIM];
__device__ __nv_bfloat16 g_actA_l[(size_t)BATCH * DIM];
__device__ __nv_bfloat16 g_actB_h[(size_t)BATCH * DIM];
__device__ __nv_bfloat16 g_actB_l[(size_t)BATCH * DIM];
__device__ __nv_bfloat16 g_mc_h[(size_t)BATCH * DIM];
__device__ __nv_bfloat16 g_mc_l[(size_t)BATCH * DIM];

// ---------------- helpers ----------------
__device__ __forceinline__ uint32_t cvt_bf16x2(float lo_elem, float hi_elem) {
    uint32_t r;
    asm("cvt.rn.bf16x2.f32 %0, %1, %2;" : "=r"(r) : "f"(hi_elem), "f"(lo_elem));
    return r;
}
__device__ __forceinline__ void split2(float a, float b, uint32_t& h, uint32_t& l) {
    h = cvt_bf16x2(a, b);
    float ha = __uint_as_float(h << 16);
    float hb = __uint_as_float(h & 0xffff0000u);
    l = cvt_bf16x2(a - ha, b - hb);
}
__device__ __forceinline__ void ldsm4(uint32_t addr, uint32_t& r0, uint32_t& r1,
                                      uint32_t& r2, uint32_t& r3) {
    asm volatile("ldmatrix.sync.aligned.m8n8.x4.shared.b16 {%0,%1,%2,%3}, [%4];"
                 : "=r"(r0), "=r"(r1), "=r"(r2), "=r"(r3) : "r"(addr));
}
__device__ __forceinline__ void ldsm4t(uint32_t addr, uint32_t& r0, uint32_t& r1,
                                       uint32_t& r2, uint32_t& r3) {
    asm volatile("ldmatrix.sync.aligned.m8n8.x4.trans.shared.b16 {%0,%1,%2,%3}, [%4];"
                 : "=r"(r0), "=r"(r1), "=r"(r2), "=r"(r3) : "r"(addr));
}
__device__ __forceinline__ void mma16816(float* c, const uint32_t* a, const uint32_t* b) {
    asm volatile(
        "mma.sync.aligned.m16n8k16.row.col.f32.bf16.bf16.f32 "
        "{%0,%1,%2,%3}, {%4,%5,%6,%7}, {%8,%9}, {%0,%1,%2,%3};"
        : "+f"(c[0]), "+f"(c[1]), "+f"(c[2]), "+f"(c[3])
        : "r"(a[0]), "r"(a[1]), "r"(a[2]), "r"(a[3]), "r"(b[0]), "r"(b[1]));
}

// ---------------- pack kernels ----------------
__global__ void pack_wei(const float* __restrict__ We, const float* __restrict__ Wi) {
    size_t i = (size_t)blockIdx.x * blockDim.x + threadIdx.x;
    const size_t total = (size_t)NLAY * DIM * 2 * DIM;
    if (i >= total) return;
    int l = (int)(i / ((size_t)DIM * 2 * DIM));
    size_t r = i % ((size_t)DIM * 2 * DIM);
    int k = (int)(r / (2 * DIM));
    int n = (int)(r % (2 * DIM));
    int mc = n >> 5, rr = n & 31;
    const float* src;
    int h;
    if (rr < 16) { src = We; h = rr; } else { src = Wi; h = rr - 16; }
    float v = src[(((size_t)l * NMC + mc) * DIM + k) * HW + h];
    __nv_bfloat16 hb = __float2bfloat16(v);
    g_w_h[OFF_WEI + i] = hb;
    g_w_l[OFF_WEI + i] = __float2bfloat16(v - __bfloat162float(hb));
}

__global__ void pack_split(const float* __restrict__ src, __nv_bfloat16* __restrict__ dh,
                           __nv_bfloat16* __restrict__ dl, size_t total) {
    size_t i = ((size_t)blockIdx.x * blockDim.x + threadIdx.x) * 4;
    if (i >= total) return;
    float4 v = *(const float4*)(src + i);
    uint32_t h0, l0, h1, l1;
    split2(v.x, v.y, h0, l0);
    split2(v.z, v.w, h1, l1);
    *(uint2*)(dh + i) = make_uint2(h0, h1);
    *(uint2*)(dl + i) = make_uint2(l0, l1);
}

__global__ void pack_bias_kernel(const float* __restrict__ be, const float* __restrict__ bi) {
    int i = blockIdx.x * blockDim.x + threadIdx.x;
    if (i >= NLAY * 2 * DIM) return;
    int l = i / (2 * DIM);
    int n = i % (2 * DIM);
    int mc = n >> 5, rr = n & 31;
    g_bei[i] = (rr < 16) ? be[l * DIM + mc * HW + rr] : bi[l * DIM + mc * HW + (rr - 16)];
}

// bvo[l][n] = bv[l] @ Wo[l][:,n] + bo[l][n]
__global__ void bvo_kernel(const float* __restrict__ bv, const float* __restrict__ Wo,
                           const float* __restrict__ bo) {
    int l = blockIdx.y;
    int n = blockIdx.x * 256 + threadIdx.x;
    const float* w = Wo + (size_t)l * SQ + n;
    const float* b = bv + l * DIM;
    float s = bo[l * DIM + n];
    for (int k = 0; k < DIM; k++) s += b[k] * w[(size_t)k * DIM];
    g_bvo[l * DIM + n] = s;
}

// b3[l][n] = blat[l] @ Wvo_f[l][:,n] + bvo[l][n]
__global__ void b3_kernel(const float* __restrict__ blat) {
    int l = blockIdx.y;
    int n = blockIdx.x * 256 + threadIdx.x;
    const float* w = g_wvo_f + (size_t)l * SQ + n;
    const float* b = blat + l * DIM;
    float s = g_bvo[l * DIM + n];
    for (int k = 0; k < DIM; k++) s += b[k] * w[(size_t)k * DIM];
    g_b3[l * DIM + n] = s;
}

// ---------------- bf16x3 HMMA GEMM, register-staged double buffer ----------------
// EPI 0: bias + hi/lo split out
// EPI 1: fused minicolumn epilogue (wide GEMM): relu, block-diag lat, mc out
// EPI 2: bias + fp32 out + split      EPI 3: bias + fp32 out += + split
// BATCH6: 6 contiguous matrices; l = by>>3 selects W (A/out contiguous)
template <int EPI, bool BATCH6>
__global__ __launch_bounds__(256, 1)
void bgemm(const __nv_bfloat16* __restrict__ Ah, const __nv_bfloat16* __restrict__ Al,
           const __nv_bfloat16* __restrict__ Wh, const __nv_bfloat16* __restrict__ Wl,
           const float* __restrict__ bias,
           __nv_bfloat16* __restrict__ oHi, __nv_bfloat16* __restrict__ oLo,
           float* __restrict__ oF, int N,
           const float* __restrict__ mcW, const float* __restrict__ mcB) {
    extern __shared__ __nv_bfloat16 smem[];
    __nv_bfloat16* sAh = smem;
    __nv_bfloat16* sAl = sAh + 2 * BM * AST;
    __nv_bfloat16* sWh = sAl + 2 * BM * AST;
    __nv_bfloat16* sWl = sWh + 2 * BK * WST;
    const uint32_t sAh_u = (uint32_t)__cvta_generic_to_shared(sAh);
    const uint32_t sAl_u = (uint32_t)__cvta_generic_to_shared(sAl);
    const uint32_t sWh_u = (uint32_t)__cvta_generic_to_shared(sWh);
    const uint32_t sWl_u = (uint32_t)__cvta_generic_to_shared(sWl);

    const int tid = threadIdx.x;
    const int lane = tid & 31, wid = tid >> 5;
    const int wm = wid >> 2, wn = wid & 3;
    const int bx = blockIdx.x, by = blockIdx.y;

    if (BATCH6) {
        size_t ws = (size_t)(by >> 3) * SQ;
        Wh += ws; Wl += ws;
    }

    const char* pAh = (const char*)Ah + (size_t)by * BM * (DIM * 2);
    const char* pAl = (const char*)Al + (size_t)by * BM * (DIM * 2);
    const char* pWh = (const char*)Wh + (size_t)bx * BN * 2;
    const char* pWl = (const char*)Wl + (size_t)bx * BN * 2;
    const size_t wrow_b = (size_t)N * 2;

    int sA[2], sW[2];
    size_t gA[2], gW[2];
#pragma unroll
    for (int i = 0; i < 2; i++) {
        int idx = i * 256 + tid;
        int ar = idx >> 2, ac = idx & 3;
        gA[i] = (size_t)ar * (DIM * 2) + (size_t)ac * 16;
        sA[i] = ar * AST + ac * 8;
        int wr = idx >> 4, wc = idx & 15;
        gW[i] = (size_t)wr * wrow_b + (size_t)wc * 16;
        sW[i] = wr * WST + wc * 8;
    }

    float acc[4][4][4];
#pragma unroll
    for (int mt = 0; mt < 4; mt++)
#pragma unroll
        for (int nt = 0; nt < 4; nt++)
#pragma unroll
            for (int q = 0; q < 4; q++) acc[mt][nt][q] = 0.f;

    uint4 ra_h[2], ra_l[2], rw_h[2], rw_l[2];
#pragma unroll
    for (int i = 0; i < 2; i++) {
        ra_h[i] = *(const uint4*)(pAh + gA[i]);
        ra_l[i] = *(const uint4*)(pAl + gA[i]);
        rw_h[i] = *(const uint4*)(pWh + gW[i]);
        rw_l[i] = *(const uint4*)(pWl + gW[i]);
    }
#pragma unroll
    for (int i = 0; i < 2; i++) {
        *(uint4*)(sAh + sA[i]) = ra_h[i];
        *(uint4*)(sAl + sA[i]) = ra_l[i];
        *(uint4*)(sWh + sW[i]) = rw_h[i];
        *(uint4*)(sWl + sW[i]) = rw_l[i];
    }
    __syncthreads();

    const int lrow = lane & 15;
    const int lcol8 = (lane >> 4) * 8;

    for (int t = 0; t < NTCH; t++) {
        const int cur = t & 1;
        if (t + 1 < NTCH) {
            const size_t cbA = (size_t)(t + 1) * (BK * 2);
            const size_t cbW = (size_t)(t + 1) * BK * wrow_b;
#pragma unroll
            for (int i = 0; i < 2; i++) {
                ra_h[i] = *(const uint4*)(pAh + gA[i] + cbA);
                ra_l[i] = *(const uint4*)(pAl + gA[i] + cbA);
                rw_h[i] = *(const uint4*)(pWh + gW[i] + cbW);
                rw_l[i] = *(const uint4*)(pWl + gW[i] + cbW);
            }
        }

#pragma unroll
        for (int ks = 0; ks < 2; ks++) {
            uint32_t ah[4][4], al[4][4], bh[4][2], bl[4][2];
#pragma unroll
            for (int mt = 0; mt < 4; mt++) {
                uint32_t off = (uint32_t)((cur * BM + wm * 64 + mt * 16 + lrow) * AST +
                                          ks * 16 + lcol8) * 2;
                ldsm4(sAh_u + off, ah[mt][0], ah[mt][1], ah[mt][2], ah[mt][3]);
                ldsm4(sAl_u + off, al[mt][0], al[mt][1], al[mt][2], al[mt][3]);
            }
#pragma unroll
            for (int np = 0; np < 2; np++) {
                uint32_t off = (uint32_t)((cur * BK + ks * 16 + lrow) * WST +
                                          wn * 32 + np * 16 + lcol8) * 2;
                uint32_t r0, r1, r2, r3;
                ldsm4t(sWh_u + off, r0, r1, r2, r3);
                bh[np * 2][0] = r0; bh[np * 2][1] = r1;
                bh[np * 2 + 1][0] = r2; bh[np * 2 + 1][1] = r3;
                ldsm4t(sWl_u + off, r0, r1, r2, r3);
                bl[np * 2][0] = r0; bl[np * 2][1] = r1;
                bl[np * 2 + 1][0] = r2; bl[np * 2 + 1][1] = r3;
            }
#pragma unroll
            for (int mt = 0; mt < 4; mt++)
#pragma unroll
                for (int nt = 0; nt < 4; nt++) mma16816(acc[mt][nt], ah[mt], bh[nt]);
#pragma unroll
            for (int mt = 0; mt < 4; mt++)
#pragma unroll
                for (int nt = 0; nt < 4; nt++) mma16816(acc[mt][nt], ah[mt], bl[nt]);
#pragma unroll
            for (int mt = 0; mt < 4; mt++)
#pragma unroll
                for (int nt = 0; nt < 4; nt++) mma16816(acc[mt][nt], al[mt], bh[nt]);
        }

        if (t + 1 < NTCH) {
            const int nxt = cur ^ 1;
#pragma unroll
            for (int i = 0; i < 2; i++) {
                *(uint4*)(sAh + nxt * BM * AST + sA[i]) = ra_h[i];
                *(uint4*)(sAl + nxt * BM * AST + sA[i]) = ra_l[i];
                *(uint4*)(sWh + nxt * BK * WST + sW[i]) = rw_h[i];
                *(uint4*)(sWl + nxt * BK * WST + sW[i]) = rw_l[i];
            }
            __syncthreads();
        }
    }

    // ---------------- epilogue ----------------
    const int g = lane >> 2;
    const int tg = lane & 3;

    if (EPI == 1) {
        // fused minicolumn: stage relu'd exc|inh tile in smem, apply block-diag, emit mc
        float* tileF = (float*)smem;
        __syncthreads();
#pragma unroll
        for (int mt = 0; mt < 4; mt++) {
            const int rl = wm * 64 + mt * 16 + g;
#pragma unroll
            for (int nt = 0; nt < 4; nt++) {
                const int cl = wn * 32 + nt * 8 + tg * 2;
                float2 bv = *(const float2*)(bias + bx * BN + cl);
                tileF[rl * TSTR + cl]           = fmaxf(acc[mt][nt][0] + bv.x, 0.f);
                tileF[rl * TSTR + cl + 1]       = fmaxf(acc[mt][nt][1] + bv.y, 0.f);
                tileF[(rl + 8) * TSTR + cl]     = fmaxf(acc[mt][nt][2] + bv.x, 0.f);
                tileF[(rl + 8) * TSTR + cl + 1] = fmaxf(acc[mt][nt][3] + bv.y, 0.f);
            }
        }
        float* sWlF = tileF + SWL_OFF;
        float* sblF = tileF + SBL_OFF;
#pragma unroll
        for (int i = 0; i < 4; i++) sWlF[i * 256 + tid] = mcW[(size_t)(bx * 4) * 256 + i * 256 + tid];
        if (tid < 64) sblF[tid] = mcB[bx * 64 + tid];
        __syncthreads();

#pragma unroll
        for (int it = 0; it < 2; it++) {
            int w = it * 256 + tid;
            int j = w & 3, row = w >> 2;
            const float* tr = tileF + row * TSTR + j * 32;
            float inh[16];
#pragma unroll
            for (int h = 0; h < 16; h++) inh[h] = tr[16 + h];
            float o[16];
#pragma unroll
            for (int k = 0; k < 16; k++) {
                float lat = sblF[j * 16 + k];
#pragma unroll
                for (int h = 0; h < 16; h++) lat += inh[h] * sWlF[j * 256 + h * 16 + k];
                o[k] = fmaxf(tr[k] - lat, 0.f);
            }
            uint32_t hu[8], lu[8];
#pragma unroll
            for (int p = 0; p < 8; p++) split2(o[2 * p], o[2 * p + 1], hu[p], lu[p]);
            size_t oo = (size_t)(by * 128 + row) * DIM + (bx * 4 + j) * 16;
            *(uint4*)(oHi + oo)     = make_uint4(hu[0], hu[1], hu[2], hu[3]);
            *(uint4*)(oHi + oo + 8) = make_uint4(hu[4], hu[5], hu[6], hu[7]);
            *(uint4*)(oLo + oo)     = make_uint4(lu[0], lu[1], lu[2], lu[3]);
            *(uint4*)(oLo + oo + 8) = make_uint4(lu[4], lu[5], lu[6], lu[7]);
        }
        return;
    }

#pragma unroll
    for (int mt = 0; mt < 4; mt++) {
        const int r0 = by * BM + wm * 64 + mt * 16 + g;
#pragma unroll
        for (int nt = 0; nt < 4; nt++) {
            const int col = bx * BN + wn * 32 + nt * 8 + tg * 2;
            float2 bv = bias ? *(const float2*)(bias + col) : make_float2(0.f, 0.f);
            float2 v0, v1;
            v0.x = acc[mt][nt][0] + bv.x;  v0.y = acc[mt][nt][1] + bv.y;
            v1.x = acc[mt][nt][2] + bv.x;  v1.y = acc[mt][nt][3] + bv.y;
            if (EPI >= 2) {
                float* p0 = oF + (size_t)r0 * N + col;
                float* p1 = oF + (size_t)(r0 + 8) * N + col;
                if (EPI == 3) {
                    float2 o0 = *(const float2*)p0;
                    float2 o1 = *(const float2*)p1;
                    v0.x += o0.x; v0.y += o0.y; v1.x += o1.x; v1.y += o1.y;
                }
                *(float2*)p0 = v0;
                *(float2*)p1 = v1;
            }
            uint32_t h0, l0, h1, l1;
            split2(v0.x, v0.y, h0, l0);
            split2(v1.x, v1.y, h1, l1);
            *(uint32_t*)(oHi + (size_t)r0 * N + col)       = h0;
            *(uint32_t*)(oLo + (size_t)r0 * N + col)       = l0;
            *(uint32_t*)(oHi + (size_t)(r0 + 8) * N + col) = h1;
            *(uint32_t*)(oLo + (size_t)(r0 + 8) * N + col) = l1;
        }
    }
}

// ---------------- driver ----------------
extern "C" void kernel_launch(void* const* d_in, const int* in_sizes, int n_in,
                              void* d_out, int out_size) {
    const float* x    = (const float*)d_in[0];
    const float* We   = (const float*)d_in[1];
    const float* be   = (const float*)d_in[2];
    const float* Wi   = (const float*)d_in[3];
    const float* bi   = (const float*)d_in[4];
    const float* Wl   = (const float*)d_in[5];
    const float* bl   = (const float*)d_in[6];
    const float* Wlat = (const float*)d_in[7];
    const float* blat = (const float*)d_in[8];
    const float* Wv   = (const float*)d_in[9];
    const float* bv   = (const float*)d_in[10];
    const float* Wo   = (const float*)d_in[11];
    const float* bo   = (const float*)d_in[12];
    const float* fbW  = (const float*)d_in[13];
    const float* fbb  = (const float*)d_in[14];
    float* out = (float*)d_out;

    const size_t BD = (size_t)BATCH * DIM;

    __nv_bfloat16 *w_h, *w_l, *actA_h, *actA_l, *actB_h, *actB_l, *mc_h, *mc_l;
    float *bei_p, *b3_p, *wvo_f;
    cudaGetSymbolAddress((void**)&w_h, g_w_h);
    cudaGetSymbolAddress((void**)&w_l, g_w_l);
    cudaGetSymbolAddress((void**)&actA_h, g_actA_h);
    cudaGetSymbolAddress((void**)&actA_l, g_actA_l);
    cudaGetSymbolAddress((void**)&actB_h, g_actB_h);
    cudaGetSymbolAddress((void**)&actB_l, g_actB_l);
    cudaGetSymbolAddress((void**)&mc_h, g_mc_h);
    cudaGetSymbolAddress((void**)&mc_l, g_mc_l);
    cudaGetSymbolAddress((void**)&bei_p, g_bei);
    cudaGetSymbolAddress((void**)&b3_p, g_b3);
    cudaGetSymbolAddress((void**)&wvo_f, g_wvo_f);

    cudaFuncSetAttribute((const void*)bgemm<0, false>, cudaFuncAttributeMaxDynamicSharedMemorySize, SMEM_BYTES);
    cudaFuncSetAttribute((const void*)bgemm<0, true>,  cudaFuncAttributeMaxDynamicSharedMemorySize, SMEM_BYTES);
    cudaFuncSetAttribute((const void*)bgemm<2, true>,  cudaFuncAttributeMaxDynamicSharedMemorySize, SMEM_BYTES);
    cudaFuncSetAttribute((const void*)bgemm<1, false>, cudaFuncAttributeMaxDynamicSharedMemorySize, SMEM_BYTES);
    cudaFuncSetAttribute((const void*)bgemm<2, false>, cudaFuncAttributeMaxDynamicSharedMemorySize, SMEM_BYTES);
    cudaFuncSetAttribute((const void*)bgemm<3, false>, cudaFuncAttributeMaxDynamicSharedMemorySize, SMEM_BYTES);

    // ---- packs + weight-side precompute ----
    {
        size_t tw = (size_t)NLAY * DIM * 2 * DIM;
        pack_wei<<<(unsigned)((tw + 255) / 256), 256>>>(We, Wi);
        pack_split<<<(unsigned)(6 * SQ / 4 / 256), 256>>>(Wlat, w_h + OFF_LAT, w_l + OFF_LAT, 6 * SQ);
        pack_split<<<(unsigned)(6 * SQ / 4 / 256), 256>>>(Wv,   w_h + OFF_V,   w_l + OFF_V,   6 * SQ);
        pack_split<<<(unsigned)(6 * SQ / 4 / 256), 256>>>(Wo,   w_h + OFF_O,   w_l + OFF_O,   6 * SQ);
        pack_split<<<(unsigned)(5 * SQ / 4 / 256), 256>>>(fbW,  w_h + OFF_FB,  w_l + OFF_FB,  5 * SQ);
        pack_split<<<(unsigned)(BD / 4 / 256), 256>>>(x, actA_h, actA_l, BD);
        pack_bias_kernel<<<(NLAY * 2 * DIM + 255) / 256, 256>>>(be, bi);
        bvo_kernel<<<dim3(4, NLAY), 256>>>(bv, Wo, bo);
        // Wvo[l] = Wv[l] @ Wo[l]  (hi/lo split + fp32 copy for b3)
        bgemm<2, true><<<dim3(8, 48), 256, SMEM_BYTES>>>(
            w_h + OFF_V, w_l + OFF_V, w_h + OFF_O, w_l + OFF_O, nullptr,
            w_h + OFF_VO, w_l + OFF_VO, wvo_f, 1024, nullptr, nullptr);
        // W3[l] = Wlat[l] @ Wvo[l]
        bgemm<0, true><<<dim3(8, 48), 256, SMEM_BYTES>>>(
            w_h + OFF_LAT, w_l + OFF_LAT, w_h + OFF_VO, w_l + OFF_VO, nullptr,
            w_h + OFF_W3, w_l + OFF_W3, nullptr, 1024, nullptr, nullptr);
        // b3[l] = blat[l] @ Wvo[l] + bvo[l]
        b3_kernel<<<dim3(4, NLAY), 256>>>(blat);
    }

    dim3 blk(256);
    dim3 grid_wide(2 * DIM / BN, BATCH / BM);
    dim3 grid_sq(DIM / BN, BATCH / BM);

    for (int l = 0; l < NLAY; l++) {
        const size_t weOff = OFF_WEI + (size_t)l * 2048 * 1024;
        // fused: exc|inh GEMM + relu + minicolumn block-diag -> mc hi/lo
        bgemm<1, false><<<grid_wide, blk, SMEM_BYTES>>>(
            actA_h, actA_l, w_h + weOff, w_l + weOff, bei_p + l * 2048,
            mc_h, mc_l, nullptr, 2048,
            Wl + (size_t)l * NMC * HW * HW, bl + (size_t)l * NMC * HW);
        // attended = mc @ W3 + b3 -> out[l] fp32 + next act split
        bgemm<2, false><<<grid_sq, blk, SMEM_BYTES>>>(
            mc_h, mc_l, w_h + OFF_W3 + (size_t)l * SQ, w_l + OFF_W3 + (size_t)l * SQ,
            b3_p + l * DIM, actA_h, actA_l, out + (size_t)l * BD, 1024, nullptr, nullptr);
    }

    // feedback: out[idx] += fb_in @ fbW[i] + fbb[i]
    __nv_bfloat16 *fin_h = actA_h, *fin_l = actA_l, *fout_h = actB_h, *fout_l = actB_l;
    for (int i = 0; i < NLAY - 1; i++) {
        int idx = NLAY - 2 - i;
        bgemm<3, false><<<grid_sq, blk, SMEM_BYTES>>>(
            fin_h, fin_l, w_h + OFF_FB + (size_t)i * SQ, w_l + OFF_FB + (size_t)i * SQ,
            fbb + (size_t)i * DIM, fout_h, fout_l, out + (size_t)idx * BD, 1024,
            nullptr, nullptr);
        __nv_bfloat16* t;
        t = fin_h; fin_h = fout_h; fout_h = t;
        t = fin_l; fin_l = fout_l; fout_l = t;
    }
}

// round 9
// speedup vs baseline: 1.6914x; 1.0291x over previous
#include <cuda_runtime.h>
#include <cuda_bf16.h>
#include <cstdint>

#define BATCH 16384
#define DIM   1024
#define NLAY  6
#define NMC   64
#define HW    16

#define BM 128
#define BN 128
#define BK 32
#define AST 40     // A smem row stride (bf16 elems)
#define WST 136    // W smem row stride (bf16 elems)
#define NTCH (DIM / BK)   // 32 K-chunks

#define SMEM_BYTES ((2 * BM * AST * 2 + 2 * BK * WST * 2) * 2)  // 75776
// fused-mc epilogue smem layout (fp32 view of same buffer):
#define TSTR 132
#define SWL_OFF (128 * TSTR)
#define SBL_OFF (SWL_OFF + 4 * 256)

// ---------------- static device scratch ----------------
#define SQ ((size_t)1048576)
#define OFF_WEI ((size_t)0)
#define OFF_LAT ((size_t)(6 * 2048 * 1024))
#define OFF_V   (OFF_LAT + 6 * SQ)
#define OFF_O   (OFF_V + 6 * SQ)
#define OFF_FB  (OFF_O + 6 * SQ)
#define OFF_VO  (OFF_FB + 5 * SQ)
#define OFF_W3  (OFF_VO + 6 * SQ)
#define WT_TOT  (OFF_W3 + 6 * SQ)

__device__ __nv_bfloat16 g_w_h[WT_TOT];
__device__ __nv_bfloat16 g_w_l[WT_TOT];
__device__ float g_bei[NLAY * 2 * DIM];   // interleaved [mc][exc16|inh16]
__device__ float g_bvo[NLAY * DIM];
__device__ float g_b3[NLAY * DIM];
__device__ float g_wvo_f[6 * SQ];         // fp32 Wvo (for exact b3)

__device__ __nv_bfloat16 g_actA_h[(size_t)BATCH * DIM];
__device__ __nv_bfloat16 g_actA_l[(size_t)BATCH * DIM];
__device__ __nv_bfloat16 g_actB_h[(size_t)BATCH * DIM];
__device__ __nv_bfloat16 g_actB_l[(size_t)BATCH * DIM];
__device__ __nv_bfloat16 g_mc_h[(size_t)BATCH * DIM];
__device__ __nv_bfloat16 g_mc_l[(size_t)BATCH * DIM];

// ---------------- helpers ----------------
__device__ __forceinline__ uint32_t cvt_bf16x2(float lo_elem, float hi_elem) {
    uint32_t r;
    asm("cvt.rn.bf16x2.f32 %0, %1, %2;" : "=r"(r) : "f"(hi_elem), "f"(lo_elem));
    return r;
}
__device__ __forceinline__ void split2(float a, float b, uint32_t& h, uint32_t& l) {
    h = cvt_bf16x2(a, b);
    float ha = __uint_as_float(h << 16);
    float hb = __uint_as_float(h & 0xffff0000u);
    l = cvt_bf16x2(a - ha, b - hb);
}
__device__ __forceinline__ void cp16(uint32_t dst, const void* src) {
    asm volatile("cp.async.cg.shared.global [%0], [%1], 16;" :: "r"(dst), "l"(src));
}
__device__ __forceinline__ void ldsm4(uint32_t addr, uint32_t& r0, uint32_t& r1,
                                      uint32_t& r2, uint32_t& r3) {
    asm volatile("ldmatrix.sync.aligned.m8n8.x4.shared.b16 {%0,%1,%2,%3}, [%4];"
                 : "=r"(r0), "=r"(r1), "=r"(r2), "=r"(r3) : "r"(addr));
}
__device__ __forceinline__ void ldsm4t(uint32_t addr, uint32_t& r0, uint32_t& r1,
                                       uint32_t& r2, uint32_t& r3) {
    asm volatile("ldmatrix.sync.aligned.m8n8.x4.trans.shared.b16 {%0,%1,%2,%3}, [%4];"
                 : "=r"(r0), "=r"(r1), "=r"(r2), "=r"(r3) : "r"(addr));
}
__device__ __forceinline__ void mma16816(float* c, const uint32_t* a, const uint32_t* b) {
    asm volatile(
        "mma.sync.aligned.m16n8k16.row.col.f32.bf16.bf16.f32 "
        "{%0,%1,%2,%3}, {%4,%5,%6,%7}, {%8,%9}, {%0,%1,%2,%3};"
        : "+f"(c[0]), "+f"(c[1]), "+f"(c[2]), "+f"(c[3])
        : "r"(a[0]), "r"(a[1]), "r"(a[2]), "r"(a[3]), "r"(b[0]), "r"(b[1]));
}

// ---------------- pack kernels ----------------
__global__ void pack_wei(const float* __restrict__ We, const float* __restrict__ Wi) {
    size_t i = (size_t)blockIdx.x * blockDim.x + threadIdx.x;
    const size_t total = (size_t)NLAY * DIM * 2 * DIM;
    if (i >= total) return;
    int l = (int)(i / ((size_t)DIM * 2 * DIM));
    size_t r = i % ((size_t)DIM * 2 * DIM);
    int k = (int)(r / (2 * DIM));
    int n = (int)(r % (2 * DIM));
    int mc = n >> 5, rr = n & 31;
    const float* src;
    int h;
    if (rr < 16) { src = We; h = rr; } else { src = Wi; h = rr - 16; }
    float v = src[(((size_t)l * NMC + mc) * DIM + k) * HW + h];
    __nv_bfloat16 hb = __float2bfloat16(v);
    g_w_h[OFF_WEI + i] = hb;
    g_w_l[OFF_WEI + i] = __float2bfloat16(v - __bfloat162float(hb));
}

__global__ void pack_split(const float* __restrict__ src, __nv_bfloat16* __restrict__ dh,
                           __nv_bfloat16* __restrict__ dl, size_t total) {
    size_t i = ((size_t)blockIdx.x * blockDim.x + threadIdx.x) * 4;
    if (i >= total) return;
    float4 v = *(const float4*)(src + i);
    uint32_t h0, l0, h1, l1;
    split2(v.x, v.y, h0, l0);
    split2(v.z, v.w, h1, l1);
    *(uint2*)(dh + i) = make_uint2(h0, h1);
    *(uint2*)(dl + i) = make_uint2(l0, l1);
}

__global__ void pack_bias_kernel(const float* __restrict__ be, const float* __restrict__ bi) {
    int i = blockIdx.x * blockDim.x + threadIdx.x;
    if (i >= NLAY * 2 * DIM) return;
    int l = i / (2 * DIM);
    int n = i % (2 * DIM);
    int mc = n >> 5, rr = n & 31;
    g_bei[i] = (rr < 16) ? be[l * DIM + mc * HW + rr] : bi[l * DIM + mc * HW + (rr - 16)];
}

__global__ void bvo_kernel(const float* __restrict__ bv, const float* __restrict__ Wo,
                           const float* __restrict__ bo) {
    int l = blockIdx.y;
    int n = blockIdx.x * 256 + threadIdx.x;
    const float* w = Wo + (size_t)l * SQ + n;
    const float* b = bv + l * DIM;
    float s = bo[l * DIM + n];
    for (int k = 0; k < DIM; k++) s += b[k] * w[(size_t)k * DIM];
    g_bvo[l * DIM + n] = s;
}

__global__ void b3_kernel(const float* __restrict__ blat) {
    int l = blockIdx.y;
    int n = blockIdx.x * 256 + threadIdx.x;
    const float* w = g_wvo_f + (size_t)l * SQ + n;
    const float* b = blat + l * DIM;
    float s = g_bvo[l * DIM + n];
    for (int k = 0; k < DIM; k++) s += b[k] * w[(size_t)k * DIM];
    g_b3[l * DIM + n] = s;
}

// ---------------- bf16x3 HMMA GEMM, cp.async 2-stage, 2 CTAs/SM ----------------
// EPI 0: bias + hi/lo split out
// EPI 1: fused minicolumn epilogue (wide GEMM): relu, block-diag lat, mc out
// EPI 2: bias + fp32 out + split      EPI 3: bias + fp32 out += + split
// BATCH6: 6 contiguous matrices; l = by>>3 selects W
template <int EPI, bool BATCH6>
__global__ __launch_bounds__(256, 2)
void bgemm(const __nv_bfloat16* __restrict__ Ah, const __nv_bfloat16* __restrict__ Al,
           const __nv_bfloat16* __restrict__ Wh, const __nv_bfloat16* __restrict__ Wl,
           const float* __restrict__ bias,
           __nv_bfloat16* __restrict__ oHi, __nv_bfloat16* __restrict__ oLo,
           float* __restrict__ oF, int N,
           const float* __restrict__ mcW, const float* __restrict__ mcB) {
    extern __shared__ __nv_bfloat16 smem[];
    __nv_bfloat16* sAh = smem;
    __nv_bfloat16* sAl = sAh + 2 * BM * AST;
    __nv_bfloat16* sWh = sAl + 2 * BM * AST;
    __nv_bfloat16* sWl = sWh + 2 * BK * WST;
    const uint32_t sAh_u = (uint32_t)__cvta_generic_to_shared(sAh);
    const uint32_t sAl_u = (uint32_t)__cvta_generic_to_shared(sAl);
    const uint32_t sWh_u = (uint32_t)__cvta_generic_to_shared(sWh);
    const uint32_t sWl_u = (uint32_t)__cvta_generic_to_shared(sWl);

    const int tid = threadIdx.x;
    const int lane = tid & 31, wid = tid >> 5;
    const int wm = wid >> 2, wn = wid & 3;
    const int bx = blockIdx.x, by = blockIdx.y;

    if (BATCH6) {
        size_t ws = (size_t)(by >> 3) * SQ;
        Wh += ws; Wl += ws;
    }

    const char* pAh = (const char*)Ah + (size_t)by * BM * (DIM * 2);
    const char* pAl = (const char*)Al + (size_t)by * BM * (DIM * 2);
    const char* pWh = (const char*)Wh + (size_t)bx * BN * 2;
    const char* pWl = (const char*)Wl + (size_t)bx * BN * 2;
    const size_t wrow_b = (size_t)N * 2;

    uint32_t sAb[2], sWb[2];   // smem byte offsets per loader iter
    size_t gA[2], gW[2];
#pragma unroll
    for (int i = 0; i < 2; i++) {
        int idx = i * 256 + tid;
        int ar = idx >> 2, ac = idx & 3;
        gA[i] = (size_t)ar * (DIM * 2) + (size_t)ac * 16;
        sAb[i] = (uint32_t)(ar * AST + ac * 8) * 2;
        int wr = idx >> 4, wc = idx & 15;
        gW[i] = (size_t)wr * wrow_b + (size_t)wc * 16;
        sWb[i] = (uint32_t)(wr * WST + wc * 8) * 2;
    }

    auto load_async = [&](int c) {
        const int buf = c & 1;
        const uint32_t offA = (uint32_t)(buf * BM * AST * 2);
        const uint32_t offW = (uint32_t)(buf * BK * WST * 2);
        const size_t cbA = (size_t)c * (BK * 2);
        const size_t cbW = (size_t)c * BK * wrow_b;
#pragma unroll
        for (int i = 0; i < 2; i++) {
            cp16(sAh_u + offA + sAb[i], pAh + gA[i] + cbA);
            cp16(sAl_u + offA + sAb[i], pAl + gA[i] + cbA);
            cp16(sWh_u + offW + sWb[i], pWh + gW[i] + cbW);
            cp16(sWl_u + offW + sWb[i], pWl + gW[i] + cbW);
        }
        asm volatile("cp.async.commit_group;" ::: "memory");
    };

    float acc[4][4][4];
#pragma unroll
    for (int mt = 0; mt < 4; mt++)
#pragma unroll
        for (int nt = 0; nt < 4; nt++)
#pragma unroll
            for (int q = 0; q < 4; q++) acc[mt][nt][q] = 0.f;

    load_async(0);

    const int lrow = lane & 15;
    const int lcol8 = (lane >> 4) * 8;

    for (int t = 0; t < NTCH; t++) {
        const int cur = t & 1;
        asm volatile("cp.async.wait_group 0;" ::: "memory");
        __syncthreads();
        if (t + 1 < NTCH) load_async(t + 1);

#pragma unroll
        for (int ks = 0; ks < 2; ks++) {
            uint32_t ah[4][4], al[4][4], bh[4][2], bl[4][2];
#pragma unroll
            for (int mt = 0; mt < 4; mt++) {
                uint32_t off = (uint32_t)((cur * BM + wm * 64 + mt * 16 + lrow) * AST +
                                          ks * 16 + lcol8) * 2;
                ldsm4(sAh_u + off, ah[mt][0], ah[mt][1], ah[mt][2], ah[mt][3]);
                ldsm4(sAl_u + off, al[mt][0], al[mt][1], al[mt][2], al[mt][3]);
            }
#pragma unroll
            for (int np = 0; np < 2; np++) {
                uint32_t off = (uint32_t)((cur * BK + ks * 16 + lrow) * WST +
                                          wn * 32 + np * 16 + lcol8) * 2;
                uint32_t r0, r1, r2, r3;
                ldsm4t(sWh_u + off, r0, r1, r2, r3);
                bh[np * 2][0] = r0; bh[np * 2][1] = r1;
                bh[np * 2 + 1][0] = r2; bh[np * 2 + 1][1] = r3;
                ldsm4t(sWl_u + off, r0, r1, r2, r3);
                bl[np * 2][0] = r0; bl[np * 2][1] = r1;
                bl[np * 2 + 1][0] = r2; bl[np * 2 + 1][1] = r3;
            }
#pragma unroll
            for (int mt = 0; mt < 4; mt++)
#pragma unroll
                for (int nt = 0; nt < 4; nt++) mma16816(acc[mt][nt], ah[mt], bh[nt]);
#pragma unroll
            for (int mt = 0; mt < 4; mt++)
#pragma unroll
                for (int nt = 0; nt < 4; nt++) mma16816(acc[mt][nt], ah[mt], bl[nt]);
#pragma unroll
            for (int mt = 0; mt < 4; mt++)
#pragma unroll
                for (int nt = 0; nt < 4; nt++) mma16816(acc[mt][nt], al[mt], bh[nt]);
        }
        __syncthreads();   // all reads of buffer cur done before next overwrite
    }

    // ---------------- epilogue ----------------
    const int g = lane >> 2;
    const int tg = lane & 3;

    if (EPI == 1) {
        float* tileF = (float*)smem;
#pragma unroll
        for (int mt = 0; mt < 4; mt++) {
            const int rl = wm * 64 + mt * 16 + g;
#pragma unroll
            for (int nt = 0; nt < 4; nt++) {
                const int cl = wn * 32 + nt * 8 + tg * 2;
                float2 bv = *(const float2*)(bias + bx * BN + cl);
                tileF[rl * TSTR + cl]           = fmaxf(acc[mt][nt][0] + bv.x, 0.f);
                tileF[rl * TSTR + cl + 1]       = fmaxf(acc[mt][nt][1] + bv.y, 0.f);
                tileF[(rl + 8) * TSTR + cl]     = fmaxf(acc[mt][nt][2] + bv.x, 0.f);
                tileF[(rl + 8) * TSTR + cl + 1] = fmaxf(acc[mt][nt][3] + bv.y, 0.f);
            }
        }
        float* sWlF = tileF + SWL_OFF;
        float* sblF = tileF + SBL_OFF;
#pragma unroll
        for (int i = 0; i < 4; i++) sWlF[i * 256 + tid] = mcW[(size_t)(bx * 4) * 256 + i * 256 + tid];
        if (tid < 64) sblF[tid] = mcB[bx * 64 + tid];
        __syncthreads();

#pragma unroll
        for (int it = 0; it < 2; it++) {
            int w = it * 256 + tid;
            int j = w & 3, row = w >> 2;
            const float* tr = tileF + row * TSTR + j * 32;
            float inh[16];
#pragma unroll
            for (int h = 0; h < 16; h++) inh[h] = tr[16 + h];
            float o[16];
#pragma unroll
            for (int k = 0; k < 16; k++) {
                float lat = sblF[j * 16 + k];
#pragma unroll
                for (int h = 0; h < 16; h++) lat += inh[h] * sWlF[j * 256 + h * 16 + k];
                o[k] = fmaxf(tr[k] - lat, 0.f);
            }
            uint32_t hu[8], lu[8];
#pragma unroll
            for (int p = 0; p < 8; p++) split2(o[2 * p], o[2 * p + 1], hu[p], lu[p]);
            size_t oo = (size_t)(by * 128 + row) * DIM + (bx * 4 + j) * 16;
            *(uint4*)(oHi + oo)     = make_uint4(hu[0], hu[1], hu[2], hu[3]);
            *(uint4*)(oHi + oo + 8) = make_uint4(hu[4], hu[5], hu[6], hu[7]);
            *(uint4*)(oLo + oo)     = make_uint4(lu[0], lu[1], lu[2], lu[3]);
            *(uint4*)(oLo + oo + 8) = make_uint4(lu[4], lu[5], lu[6], lu[7]);
        }
        return;
    }

#pragma unroll
    for (int mt = 0; mt < 4; mt++) {
        const int r0 = by * BM + wm * 64 + mt * 16 + g;
#pragma unroll
        for (int nt = 0; nt < 4; nt++) {
            const int col = bx * BN + wn * 32 + nt * 8 + tg * 2;
            float2 bv = bias ? *(const float2*)(bias + col) : make_float2(0.f, 0.f);
            float2 v0, v1;
            v0.x = acc[mt][nt][0] + bv.x;  v0.y = acc[mt][nt][1] + bv.y;
            v1.x = acc[mt][nt][2] + bv.x;  v1.y = acc[mt][nt][3] + bv.y;
            if (EPI >= 2) {
                float* p0 = oF + (size_t)r0 * N + col;
                float* p1 = oF + (size_t)(r0 + 8) * N + col;
                if (EPI == 3) {
                    float2 o0 = *(const float2*)p0;
                    float2 o1 = *(const float2*)p1;
                    v0.x += o0.x; v0.y += o0.y; v1.x += o1.x; v1.y += o1.y;
                }
                *(float2*)p0 = v0;
                *(float2*)p1 = v1;
            }
            uint32_t h0, l0, h1, l1;
            split2(v0.x, v0.y, h0, l0);
            split2(v1.x, v1.y, h1, l1);
            *(uint32_t*)(oHi + (size_t)r0 * N + col)       = h0;
            *(uint32_t*)(oLo + (size_t)r0 * N + col)       = l0;
            *(uint32_t*)(oHi + (size_t)(r0 + 8) * N + col) = h1;
            *(uint32_t*)(oLo + (size_t)(r0 + 8) * N + col) = l1;
        }
    }
}

// ---------------- driver ----------------
extern "C" void kernel_launch(void* const* d_in, const int* in_sizes, int n_in,
                              void* d_out, int out_size) {
    const float* x    = (const float*)d_in[0];
    const float* We   = (const float*)d_in[1];
    const float* be   = (const float*)d_in[2];
    const float* Wi   = (const float*)d_in[3];
    const float* bi   = (const float*)d_in[4];
    const float* Wl   = (const float*)d_in[5];
    const float* bl   = (const float*)d_in[6];
    const float* Wlat = (const float*)d_in[7];
    const float* blat = (const float*)d_in[8];
    const float* Wv   = (const float*)d_in[9];
    const float* bv   = (const float*)d_in[10];
    const float* Wo   = (const float*)d_in[11];
    const float* bo   = (const float*)d_in[12];
    const float* fbW  = (const float*)d_in[13];
    const float* fbb  = (const float*)d_in[14];
    float* out = (float*)d_out;

    const size_t BD = (size_t)BATCH * DIM;

    __nv_bfloat16 *w_h, *w_l, *actA_h, *actA_l, *actB_h, *actB_l, *mc_h, *mc_l;
    float *bei_p, *b3_p, *wvo_f;
    cudaGetSymbolAddress((void**)&w_h, g_w_h);
    cudaGetSymbolAddress((void**)&w_l, g_w_l);
    cudaGetSymbolAddress((void**)&actA_h, g_actA_h);
    cudaGetSymbolAddress((void**)&actA_l, g_actA_l);
    cudaGetSymbolAddress((void**)&actB_h, g_actB_h);
    cudaGetSymbolAddress((void**)&actB_l, g_actB_l);
    cudaGetSymbolAddress((void**)&mc_h, g_mc_h);
    cudaGetSymbolAddress((void**)&mc_l, g_mc_l);
    cudaGetSymbolAddress((void**)&bei_p, g_bei);
    cudaGetSymbolAddress((void**)&b3_p, g_b3);
    cudaGetSymbolAddress((void**)&wvo_f, g_wvo_f);

    cudaFuncSetAttribute((const void*)bgemm<0, false>, cudaFuncAttributeMaxDynamicSharedMemorySize, SMEM_BYTES);
    cudaFuncSetAttribute((const void*)bgemm<0, true>,  cudaFuncAttributeMaxDynamicSharedMemorySize, SMEM_BYTES);
    cudaFuncSetAttribute((const void*)bgemm<2, true>,  cudaFuncAttributeMaxDynamicSharedMemorySize, SMEM_BYTES);
    cudaFuncSetAttribute((const void*)bgemm<1, false>, cudaFuncAttributeMaxDynamicSharedMemorySize, SMEM_BYTES);
    cudaFuncSetAttribute((const void*)bgemm<2, false>, cudaFuncAttributeMaxDynamicSharedMemorySize, SMEM_BYTES);
    cudaFuncSetAttribute((const void*)bgemm<3, false>, cudaFuncAttributeMaxDynamicSharedMemorySize, SMEM_BYTES);

    // ---- packs + weight-side precompute ----
    {
        size_t tw = (size_t)NLAY * DIM * 2 * DIM;
        pack_wei<<<(unsigned)((tw + 255) / 256), 256>>>(We, Wi);
        pack_split<<<(unsigned)(6 * SQ / 4 / 256), 256>>>(Wlat, w_h + OFF_LAT, w_l + OFF_LAT, 6 * SQ);
        pack_split<<<(unsigned)(6 * SQ / 4 / 256), 256>>>(Wv,   w_h + OFF_V,   w_l + OFF_V,   6 * SQ);
        pack_split<<<(unsigned)(6 * SQ / 4 / 256), 256>>>(Wo,   w_h + OFF_O,   w_l + OFF_O,   6 * SQ);
        pack_split<<<(unsigned)(5 * SQ / 4 / 256), 256>>>(fbW,  w_h + OFF_FB,  w_l + OFF_FB,  5 * SQ);
        pack_split<<<(unsigned)(BD / 4 / 256), 256>>>(x, actA_h, actA_l, BD);
        pack_bias_kernel<<<(NLAY * 2 * DIM + 255) / 256, 256>>>(be, bi);
        bvo_kernel<<<dim3(4, NLAY), 256>>>(bv, Wo, bo);
        bgemm<2, true><<<dim3(8, 48), 256, SMEM_BYTES>>>(
            w_h + OFF_V, w_l + OFF_V, w_h + OFF_O, w_l + OFF_O, nullptr,
            w_h + OFF_VO, w_l + OFF_VO, wvo_f, 1024, nullptr, nullptr);
        bgemm<0, true><<<dim3(8, 48), 256, SMEM_BYTES>>>(
            w_h + OFF_LAT, w_l + OFF_LAT, w_h + OFF_VO, w_l + OFF_VO, nullptr,
            w_h + OFF_W3, w_l + OFF_W3, nullptr, 1024, nullptr, nullptr);
        b3_kernel<<<dim3(4, NLAY), 256>>>(blat);
    }

    dim3 blk(256);
    dim3 grid_wide(2 * DIM / BN, BATCH / BM);
    dim3 grid_sq(DIM / BN, BATCH / BM);

    for (int l = 0; l < NLAY; l++) {
        const size_t weOff = OFF_WEI + (size_t)l * 2048 * 1024;
        bgemm<1, false><<<grid_wide, blk, SMEM_BYTES>>>(
            actA_h, actA_l, w_h + weOff, w_l + weOff, bei_p + l * 2048,
            mc_h, mc_l, nullptr, 2048,
            Wl + (size_t)l * NMC * HW * HW, bl + (size_t)l * NMC * HW);
        bgemm<2, false><<<grid_sq, blk, SMEM_BYTES>>>(
            mc_h, mc_l, w_h + OFF_W3 + (size_t)l * SQ, w_l + OFF_W3 + (size_t)l * SQ,
            b3_p + l * DIM, actA_h, actA_l, out + (size_t)l * BD, 1024, nullptr, nullptr);
    }

    __nv_bfloat16 *fin_h = actA_h, *fin_l = actA_l, *fout_h = actB_h, *fout_l = actB_l;
    for (int i = 0; i < NLAY - 1; i++) {
        int idx = NLAY - 2 - i;
        bgemm<3, false><<<grid_sq, blk, SMEM_BYTES>>>(
            fin_h, fin_l, w_h + OFF_FB + (size_t)i * SQ, w_l + OFF_FB + (size_t)i * SQ,
            fbb + (size_t)i * DIM, fout_h, fout_l, out + (size_t)idx * BD, 1024,
            nullptr, nullptr);
        __nv_bfloat16* t;
        t = fin_h; fin_h = fout_h; fout_h = t;
        t = fin_l; fin_l = fout_l; fout_l = t;
    }
}